// round 1
// baseline (speedup 1.0000x reference)
#include <cuda_runtime.h>
#include <math_constants.h>

#define D 64
#define NM 2048
#define NP 8192
#define SPLIT_M 8
#define SPLIT_P 2

// ---------------- device scratch (no allocations allowed) ----------------
__device__ float g_aggr_mol[NM * D];
__device__ float g_cnt_mol[NM];
__device__ float g_aggr_prot[NP * D];
__device__ float g_cnt_prot[NP];
__device__ float g_hmol[NM * D];
__device__ float g_hprot[NP * D];
__device__ float g_Qm[NM * D], g_Km[NM * D], g_Vm[NM * D];
__device__ float g_Qp[NP * D], g_Kp[NP * D], g_Vp[NP * D];
__device__ float g_part_mol[SPLIT_M * NM * 4 * 18];
__device__ float g_part_prot[SPLIT_P * NP * 4 * 18];

// ---------------- zero accumulators ----------------
__global__ void zero_all() {
    int i = blockIdx.x * blockDim.x + threadIdx.x;
    int stride = gridDim.x * blockDim.x;
    for (int j = i; j < NM * D; j += stride) g_aggr_mol[j] = 0.f;
    for (int j = i; j < NP * D; j += stride) g_aggr_prot[j] = 0.f;
    for (int j = i; j < NM; j += stride) g_cnt_mol[j] = 0.f;
    for (int j = i; j < NP; j += stride) g_cnt_prot[j] = 0.f;
}

// ---------------- GINE edge message + scatter-mean (sum + count) ----------------
// 16 threads per edge, each handles one float4 chunk of the 64-dim message.
__global__ void edge_scatter(const float* __restrict__ x, const int* __restrict__ ei,
                             const float* __restrict__ ea, float* __restrict__ aggr,
                             float* __restrict__ cnt, int E) {
    int idx = blockIdx.x * blockDim.x + threadIdx.x;
    if (idx >= E * 16) return;
    int e = idx >> 4;
    int c = idx & 15;
    int src = ei[e];
    int dst = ei[E + e];
    float4 xv = __ldg((const float4*)(x + (size_t)src * D) + c);
    float4 ev = __ldg((const float4*)(ea + (size_t)e * D) + c);
    float4 m;
    m.x = fmaxf(xv.x + ev.x, 0.f);
    m.y = fmaxf(xv.y + ev.y, 0.f);
    m.z = fmaxf(xv.z + ev.z, 0.f);
    m.w = fmaxf(xv.w + ev.w, 0.f);
    float* a = aggr + (size_t)dst * D + c * 4;
    atomicAdd(a + 0, m.x);
    atomicAdd(a + 1, m.y);
    atomicAdd(a + 2, m.z);
    atomicAdd(a + 3, m.w);
    if (c == 0) atomicAdd(&cnt[dst], 1.0f);
}

// ---------------- GINE node update (MLP + outer relu) fused with Q/K/V projection ----------------
// One block (64 threads) per node. 5 GEMV-64 passes.
__global__ void gine_update_proj(const float* __restrict__ x, const float* __restrict__ aggr,
                                 const float* __restrict__ cnt,
                                 const float* __restrict__ w1, const float* __restrict__ b1,
                                 const float* __restrict__ w2, const float* __restrict__ b2,
                                 const float* __restrict__ wq, const float* __restrict__ bq,
                                 const float* __restrict__ wk, const float* __restrict__ bk,
                                 const float* __restrict__ wv, const float* __restrict__ bv,
                                 float* __restrict__ h_out, float* __restrict__ Qo,
                                 float* __restrict__ Ko, float* __restrict__ Vo) {
    __shared__ float s0[D];
    __shared__ float s1[D];
    __shared__ float sh[D];
    int n = blockIdx.x;
    int j = threadIdx.x;
    float inv = 1.f / fmaxf(cnt[n], 1.f);
    s0[j] = x[(size_t)n * D + j] + aggr[(size_t)n * D + j] * inv;
    __syncthreads();
    float a = b1[j];
#pragma unroll 8
    for (int i = 0; i < D; i++) a = fmaf(s0[i], __ldg(&w1[i * D + j]), a);
    s1[j] = fmaxf(a, 0.f);
    __syncthreads();
    float hv = b2[j];
#pragma unroll 8
    for (int i = 0; i < D; i++) hv = fmaf(s1[i], __ldg(&w2[i * D + j]), hv);
    hv = fmaxf(hv, 0.f);  // outer relu
    sh[j] = hv;
    h_out[(size_t)n * D + j] = hv;
    __syncthreads();
    float q = bq[j], k = bk[j], v = bv[j];
#pragma unroll 8
    for (int i = 0; i < D; i++) {
        float t = sh[i];
        q = fmaf(t, __ldg(&wq[i * D + j]), q);
        k = fmaf(t, __ldg(&wk[i * D + j]), k);
        v = fmaf(t, __ldg(&wv[i * D + j]), v);
    }
    Qo[(size_t)n * D + j] = q;
    Ko[(size_t)n * D + j] = k;
    Vo[(size_t)n * D + j] = v;
}

// ---------------- split-K flash attention partials ----------------
// grid.x = Nq/64, grid.y = nsplit. 256 threads; thread t owns row (q = q0 + t>>2, h = t&3).
// Writes (m, l, acc[16]) per row per split.
__global__ __launch_bounds__(256) void attn_partial(const float* __restrict__ Q,
                                                    const float* __restrict__ K,
                                                    const float* __restrict__ V,
                                                    int Nq, int chunk,
                                                    float* __restrict__ part) {
    __shared__ float4 sK[64][16];
    __shared__ float4 sV[64][16];
    int t = threadIdx.x;
    int ql = t >> 2;
    int h = t & 3;
    int q = blockIdx.x * 64 + ql;
    int k0 = blockIdx.y * chunk;

    const float4* Qv = (const float4*)(Q + (size_t)q * D + h * 16);
    float4 q0 = Qv[0], q1 = Qv[1], q2 = Qv[2], q3 = Qv[3];

    float m = -CUDART_INF_F;
    float l = 0.f;
    float acc[16];
#pragma unroll
    for (int i = 0; i < 16; i++) acc[i] = 0.f;

    for (int kt = 0; kt < chunk; kt += 64) {
        const float4* Kg = (const float4*)(K + (size_t)(k0 + kt) * D);
        const float4* Vg = (const float4*)(V + (size_t)(k0 + kt) * D);
#pragma unroll
        for (int r = 0; r < 4; r++) {
            int idx = t + r * 256;
            int row = idx >> 4;
            int col = idx & 15;
            sK[row][col] = Kg[idx];
            sV[row][col] = Vg[idx];
        }
        __syncthreads();
#pragma unroll 4
        for (int k = 0; k < 64; k++) {
            float4 ka = sK[k][h * 4 + 0];
            float4 kb = sK[k][h * 4 + 1];
            float4 kc = sK[k][h * 4 + 2];
            float4 kd = sK[k][h * 4 + 3];
            float s = q0.x * ka.x + q0.y * ka.y + q0.z * ka.z + q0.w * ka.w;
            s += q1.x * kb.x + q1.y * kb.y + q1.z * kb.z + q1.w * kb.w;
            s += q2.x * kc.x + q2.y * kc.y + q2.z * kc.z + q2.w * kc.w;
            s += q3.x * kd.x + q3.y * kd.y + q3.z * kd.z + q3.w * kd.w;
            s *= 0.25f;  // 1/sqrt(HD=16)
            float p;
            if (s <= m) {
                p = __expf(s - m);
            } else {
                float corr = __expf(m - s);  // exp(-inf)=0 handles first iter
                m = s;
                l *= corr;
#pragma unroll
                for (int i = 0; i < 16; i++) acc[i] *= corr;
                p = 1.f;
            }
            l += p;
            float4 va = sV[k][h * 4 + 0];
            float4 vb = sV[k][h * 4 + 1];
            float4 vc = sV[k][h * 4 + 2];
            float4 vd = sV[k][h * 4 + 3];
            acc[0] += p * va.x;  acc[1] += p * va.y;  acc[2] += p * va.z;  acc[3] += p * va.w;
            acc[4] += p * vb.x;  acc[5] += p * vb.y;  acc[6] += p * vb.z;  acc[7] += p * vb.w;
            acc[8] += p * vc.x;  acc[9] += p * vc.y;  acc[10] += p * vc.z; acc[11] += p * vc.w;
            acc[12] += p * vd.x; acc[13] += p * vd.y; acc[14] += p * vd.z; acc[15] += p * vd.w;
        }
        __syncthreads();
    }
    int row = blockIdx.y * (Nq * 4) + q * 4 + h;
    float* pp = part + (size_t)row * 18;
    pp[0] = m;
    pp[1] = l;
#pragma unroll
    for (int i = 0; i < 16; i++) pp[2 + i] = acc[i];
}

// ---------------- combine partials + residual + layernorm ----------------
// One block (64 threads) per query; thread d = feature dim, head h=d>>4.
__global__ void combine_ln(const float* __restrict__ part, int S, int Nq,
                           const float* __restrict__ hres, const float* __restrict__ g,
                           const float* __restrict__ b, float* __restrict__ out) {
    __shared__ float red[D];
    __shared__ float red2[D];
    int q = blockIdx.x;
    int d = threadIdx.x;
    int h = d >> 4;
    int i = d & 15;
    int rowbase = q * 4 + h;

    float M = -CUDART_INF_F;
    for (int s = 0; s < S; s++) M = fmaxf(M, part[(size_t)(s * Nq * 4 + rowbase) * 18]);
    float num = 0.f, den = 0.f;
    for (int s = 0; s < S; s++) {
        const float* pp = part + (size_t)(s * Nq * 4 + rowbase) * 18;
        float e = __expf(pp[0] - M);
        den += e * pp[1];
        num += e * pp[2 + i];
    }
    float val = num / den + hres[(size_t)q * D + d];

    red[d] = val;
    red2[d] = val * val;
    __syncthreads();
    for (int off = 32; off >= 1; off >>= 1) {
        if (d < off) {
            red[d] += red[d + off];
            red2[d] += red2[d + off];
        }
        __syncthreads();
    }
    float mu = red[0] * (1.f / 64.f);
    float var = red2[0] * (1.f / 64.f) - mu * mu;
    float r = rsqrtf(var + 1e-5f);
    out[(size_t)q * D + d] = (val - mu) * r * g[d] + b[d];
}

// ---------------- launch ----------------
extern "C" void kernel_launch(void* const* d_in, const int* in_sizes, int n_in,
                              void* d_out, int out_size) {
    const float* x_mol = (const float*)d_in[0];
    const int* ei_mol = (const int*)d_in[1];
    const float* ea_mol = (const float*)d_in[2];
    const float* x_prot = (const float*)d_in[3];
    const int* ei_prot = (const int*)d_in[4];
    const float* ea_prot = (const float*)d_in[5];
    const float* mol_w1 = (const float*)d_in[6];
    const float* mol_b1 = (const float*)d_in[7];
    const float* mol_w2 = (const float*)d_in[8];
    const float* mol_b2 = (const float*)d_in[9];
    const float* prot_w1 = (const float*)d_in[10];
    const float* prot_b1 = (const float*)d_in[11];
    const float* prot_w2 = (const float*)d_in[12];
    const float* prot_b2 = (const float*)d_in[13];
    const float* mp_wq = (const float*)d_in[14];
    const float* mp_bq = (const float*)d_in[15];
    const float* mp_wk = (const float*)d_in[16];
    const float* mp_bk = (const float*)d_in[17];
    const float* mp_wv = (const float*)d_in[18];
    const float* mp_bv = (const float*)d_in[19];
    const float* pm_wq = (const float*)d_in[20];
    const float* pm_bq = (const float*)d_in[21];
    const float* pm_wk = (const float*)d_in[22];
    const float* pm_bk = (const float*)d_in[23];
    const float* pm_wv = (const float*)d_in[24];
    const float* pm_bv = (const float*)d_in[25];
    const float* ln_mol_g = (const float*)d_in[26];
    const float* ln_mol_b = (const float*)d_in[27];
    const float* ln_prot_g = (const float*)d_in[28];
    const float* ln_prot_b = (const float*)d_in[29];

    int E_mol = in_sizes[1] / 2;
    int E_prot = in_sizes[4] / 2;
    float* out = (float*)d_out;

    float *aggr_mol, *cnt_mol, *aggr_prot, *cnt_prot;
    float *hmol, *hprot, *Qm, *Km, *Vm, *Qp, *Kp, *Vp, *part_mol, *part_prot;
    cudaGetSymbolAddress((void**)&aggr_mol, g_aggr_mol);
    cudaGetSymbolAddress((void**)&cnt_mol, g_cnt_mol);
    cudaGetSymbolAddress((void**)&aggr_prot, g_aggr_prot);
    cudaGetSymbolAddress((void**)&cnt_prot, g_cnt_prot);
    cudaGetSymbolAddress((void**)&hmol, g_hmol);
    cudaGetSymbolAddress((void**)&hprot, g_hprot);
    cudaGetSymbolAddress((void**)&Qm, g_Qm);
    cudaGetSymbolAddress((void**)&Km, g_Km);
    cudaGetSymbolAddress((void**)&Vm, g_Vm);
    cudaGetSymbolAddress((void**)&Qp, g_Qp);
    cudaGetSymbolAddress((void**)&Kp, g_Kp);
    cudaGetSymbolAddress((void**)&Vp, g_Vp);
    cudaGetSymbolAddress((void**)&part_mol, g_part_mol);
    cudaGetSymbolAddress((void**)&part_prot, g_part_prot);

    zero_all<<<256, 256>>>();

    edge_scatter<<<(E_mol * 16 + 255) / 256, 256>>>(x_mol, ei_mol, ea_mol, aggr_mol, cnt_mol, E_mol);
    edge_scatter<<<(E_prot * 16 + 255) / 256, 256>>>(x_prot, ei_prot, ea_prot, aggr_prot, cnt_prot, E_prot);

    // mol nodes: Q via mp_wq (mol is query of mol->prot); K,V via pm_wk/pm_wv (mol is key/value of prot->mol)
    gine_update_proj<<<NM, 64>>>(x_mol, aggr_mol, cnt_mol, mol_w1, mol_b1, mol_w2, mol_b2,
                                 mp_wq, mp_bq, pm_wk, pm_bk, pm_wv, pm_bv, hmol, Qm, Km, Vm);
    // prot nodes: Q via pm_wq; K,V via mp_wk/mp_wv
    gine_update_proj<<<NP, 64>>>(x_prot, aggr_prot, cnt_prot, prot_w1, prot_b1, prot_w2, prot_b2,
                                 pm_wq, pm_bq, mp_wk, mp_bk, mp_wv, mp_bv, hprot, Qp, Kp, Vp);

    // mol->prot: 2048 queries over 8192 keys, 8 k-splits of 1024
    attn_partial<<<dim3(NM / 64, SPLIT_M), 256>>>(Qm, Kp, Vp, NM, NP / SPLIT_M, part_mol);
    // prot->mol: 8192 queries over 2048 keys, 2 k-splits of 1024
    attn_partial<<<dim3(NP / 64, SPLIT_P), 256>>>(Qp, Km, Vm, NP, NM / SPLIT_P, part_prot);

    combine_ln<<<NM, 64>>>(part_mol, SPLIT_M, NM, hmol, ln_mol_g, ln_mol_b, out);
    combine_ln<<<NP, 64>>>(part_prot, SPLIT_P, NP, hprot, ln_prot_g, ln_prot_b, out + NM * D);
}

// round 2
// speedup vs baseline: 1.0420x; 1.0420x over previous
#include <cuda_runtime.h>
#include <math_constants.h>

#define D 64
#define NM 2048
#define NP 8192
#define SPLIT_M 16
#define SPLIT_P 4

typedef unsigned long long u64;

// ---------------- f32x2 packed helpers (PTX-only on sm_103a) ----------------
__device__ __forceinline__ u64 f2u2(float lo, float hi) {
    u64 r; asm("mov.b64 %0,{%1,%2};" : "=l"(r) : "f"(lo), "f"(hi)); return r;
}
__device__ __forceinline__ float2 u2f2(u64 v) {
    float2 r; asm("mov.b64 {%0,%1},%2;" : "=f"(r.x), "=f"(r.y) : "l"(v)); return r;
}
__device__ __forceinline__ u64 ffma2(u64 a, u64 b, u64 c) {
    u64 d; asm("fma.rn.f32x2 %0,%1,%2,%3;" : "=l"(d) : "l"(a), "l"(b), "l"(c)); return d;
}
__device__ __forceinline__ u64 fmul2(u64 a, u64 b) {
    u64 d; asm("mul.rn.f32x2 %0,%1,%2;" : "=l"(d) : "l"(a), "l"(b)); return d;
}
__device__ __forceinline__ u64 fadd2(u64 a, u64 b) {
    u64 d; asm("add.rn.f32x2 %0,%1,%2;" : "=l"(d) : "l"(a), "l"(b)); return d;
}

// ---------------- device scratch ----------------
__device__ float g_aggr_mol[NM * D];
__device__ float g_cnt_mol[NM];
__device__ float g_aggr_prot[NP * D];
__device__ float g_cnt_prot[NP];
__device__ float g_hmol[NM * D];
__device__ float g_hprot[NP * D];
__device__ float g_Qm[NM * D], g_Km[NM * D], g_Vm[NM * D];
__device__ float g_Qp[NP * D], g_Kp[NP * D], g_Vp[NP * D];
__device__ float g_part_mol[SPLIT_M * NM * 4 * 18];
__device__ float g_part_prot[SPLIT_P * NP * 4 * 18];

// ---------------- zero accumulators ----------------
__global__ void zero_all() {
    int i = blockIdx.x * blockDim.x + threadIdx.x;
    int stride = gridDim.x * blockDim.x;
    for (int j = i; j < NM * D; j += stride) g_aggr_mol[j] = 0.f;
    for (int j = i; j < NP * D; j += stride) g_aggr_prot[j] = 0.f;
    for (int j = i; j < NM; j += stride) g_cnt_mol[j] = 0.f;
    for (int j = i; j < NP; j += stride) g_cnt_prot[j] = 0.f;
}

// ---------------- GINE edge message + scatter-mean ----------------
__global__ void edge_scatter(const float* __restrict__ x, const int* __restrict__ ei,
                             const float* __restrict__ ea, float* __restrict__ aggr,
                             float* __restrict__ cnt, int E) {
    int idx = blockIdx.x * blockDim.x + threadIdx.x;
    if (idx >= E * 16) return;
    int e = idx >> 4;
    int c = idx & 15;
    int src = ei[e];
    int dst = ei[E + e];
    float4 xv = __ldg((const float4*)(x + (size_t)src * D) + c);
    float4 ev = __ldg((const float4*)(ea + (size_t)e * D) + c);
    float4 m;
    m.x = fmaxf(xv.x + ev.x, 0.f);
    m.y = fmaxf(xv.y + ev.y, 0.f);
    m.z = fmaxf(xv.z + ev.z, 0.f);
    m.w = fmaxf(xv.w + ev.w, 0.f);
    float* a = aggr + (size_t)dst * D + c * 4;
    atomicAdd(a + 0, m.x);
    atomicAdd(a + 1, m.y);
    atomicAdd(a + 2, m.z);
    atomicAdd(a + 3, m.w);
    if (c == 0) atomicAdd(&cnt[dst], 1.0f);
}

// ---------------- GINE node update + QKV projection: 4 nodes per 256-thr block ----------------
__global__ __launch_bounds__(256) void gine_update_proj(
    const float* __restrict__ x, const float* __restrict__ aggr,
    const float* __restrict__ cnt,
    const float* __restrict__ w1, const float* __restrict__ b1,
    const float* __restrict__ w2, const float* __restrict__ b2,
    const float* __restrict__ wq, const float* __restrict__ bq,
    const float* __restrict__ wk, const float* __restrict__ bk,
    const float* __restrict__ wv, const float* __restrict__ bv,
    float* __restrict__ h_out, float* __restrict__ Qo,
    float* __restrict__ Ko, float* __restrict__ Vo) {
    __shared__ float s0[4][D];
    __shared__ float s1[4][D];
    __shared__ float sh[4][D];
    int j = threadIdx.x & 63;
    int sub = threadIdx.x >> 6;
    int n = blockIdx.x * 4 + sub;
    float inv = 1.f / fmaxf(cnt[n], 1.f);
    s0[sub][j] = x[(size_t)n * D + j] + aggr[(size_t)n * D + j] * inv;
    __syncthreads();
    // GEMV 1 with 4 independent chains
    float a0 = b1[j], a1 = 0.f, a2 = 0.f, a3 = 0.f;
#pragma unroll
    for (int i = 0; i < D; i += 4) {
        a0 = fmaf(s0[sub][i + 0], __ldg(&w1[(i + 0) * D + j]), a0);
        a1 = fmaf(s0[sub][i + 1], __ldg(&w1[(i + 1) * D + j]), a1);
        a2 = fmaf(s0[sub][i + 2], __ldg(&w1[(i + 2) * D + j]), a2);
        a3 = fmaf(s0[sub][i + 3], __ldg(&w1[(i + 3) * D + j]), a3);
    }
    s1[sub][j] = fmaxf((a0 + a1) + (a2 + a3), 0.f);
    __syncthreads();
    float h0 = b2[j], h1 = 0.f, h2 = 0.f, h3 = 0.f;
#pragma unroll
    for (int i = 0; i < D; i += 4) {
        h0 = fmaf(s1[sub][i + 0], __ldg(&w2[(i + 0) * D + j]), h0);
        h1 = fmaf(s1[sub][i + 1], __ldg(&w2[(i + 1) * D + j]), h1);
        h2 = fmaf(s1[sub][i + 2], __ldg(&w2[(i + 2) * D + j]), h2);
        h3 = fmaf(s1[sub][i + 3], __ldg(&w2[(i + 3) * D + j]), h3);
    }
    float hv = fmaxf((h0 + h1) + (h2 + h3), 0.f);
    sh[sub][j] = hv;
    h_out[(size_t)n * D + j] = hv;
    __syncthreads();
    float q0 = bq[j], q1 = 0.f, k0 = bk[j], k1 = 0.f, v0 = bv[j], v1 = 0.f;
#pragma unroll
    for (int i = 0; i < D; i += 2) {
        float t0 = sh[sub][i], t1 = sh[sub][i + 1];
        q0 = fmaf(t0, __ldg(&wq[i * D + j]), q0);
        q1 = fmaf(t1, __ldg(&wq[(i + 1) * D + j]), q1);
        k0 = fmaf(t0, __ldg(&wk[i * D + j]), k0);
        k1 = fmaf(t1, __ldg(&wk[(i + 1) * D + j]), k1);
        v0 = fmaf(t0, __ldg(&wv[i * D + j]), v0);
        v1 = fmaf(t1, __ldg(&wv[(i + 1) * D + j]), v1);
    }
    Qo[(size_t)n * D + j] = q0 + q1;
    Ko[(size_t)n * D + j] = k0 + k1;
    Vo[(size_t)n * D + j] = v0 + v1;
}

// ---------------- split-K flash attention, f32x2 packed, branchless tiled softmax ----------------
// 256 thr; thread t owns row (q = blk*64 + t>>2, h = t&3). 64-key smem tiles, 16-key sub-tiles.
__global__ __launch_bounds__(256, 3) void attn_partial(const float* __restrict__ Q,
                                                       const float* __restrict__ K,
                                                       const float* __restrict__ V,
                                                       int Nq, int chunk,
                                                       float* __restrict__ part) {
    __shared__ ulonglong2 sK[64][16];  // 64 keys x 64 floats (as 8B pairs)
    __shared__ ulonglong2 sV[64][16];
    int t = threadIdx.x;
    int ql = t >> 2;
    int h = t & 3;
    int q = blockIdx.x * 64 + ql;
    int k0 = blockIdx.y * chunk;

    // load q head slice, pre-scaled by 1/sqrt(16)
    u64 qp[8];
    {
        const float4* Qv = (const float4*)(Q + (size_t)q * D + h * 16);
#pragma unroll
        for (int r = 0; r < 4; r++) {
            float4 v = Qv[r];
            qp[r * 2 + 0] = f2u2(v.x * 0.25f, v.y * 0.25f);
            qp[r * 2 + 1] = f2u2(v.z * 0.25f, v.w * 0.25f);
        }
    }

    float m = -CUDART_INF_F;
    float l = 0.f;
    u64 acc[8];
#pragma unroll
    for (int i = 0; i < 8; i++) acc[i] = 0ull;

    for (int kt = 0; kt < chunk; kt += 64) {
        const ulonglong2* Kg = (const ulonglong2*)(K + (size_t)(k0 + kt) * D);
        const ulonglong2* Vg = (const ulonglong2*)(V + (size_t)(k0 + kt) * D);
#pragma unroll
        for (int r = 0; r < 4; r++) {
            int idx = t + r * 256;
            ((ulonglong2*)sK)[idx] = Kg[idx];
            ((ulonglong2*)sV)[idx] = Vg[idx];
        }
        __syncthreads();

        for (int sub = 0; sub < 4; sub++) {
            float s[16];
            const ulonglong2* krow = &sK[sub * 16][h * 4];
#pragma unroll
            for (int kk = 0; kk < 16; kk++) {
                const ulonglong2* kr = krow + kk * 16;
                ulonglong2 ka = kr[0], kb = kr[1], kc = kr[2], kd = kr[3];
                u64 sa = fmul2(qp[0], ka.x);
                u64 sb = fmul2(qp[1], ka.y);
                sa = ffma2(qp[2], kb.x, sa);
                sb = ffma2(qp[3], kb.y, sb);
                sa = ffma2(qp[4], kc.x, sa);
                sb = ffma2(qp[5], kc.y, sb);
                sa = ffma2(qp[6], kd.x, sa);
                sb = ffma2(qp[7], kd.y, sb);
                float2 f = u2f2(fadd2(sa, sb));
                s[kk] = f.x + f.y;
            }
            // sub-tile max (tree)
            float tm01 = fmaxf(s[0], s[1]), tm23 = fmaxf(s[2], s[3]);
            float tm45 = fmaxf(s[4], s[5]), tm67 = fmaxf(s[6], s[7]);
            float tm89 = fmaxf(s[8], s[9]), tmab = fmaxf(s[10], s[11]);
            float tmcd = fmaxf(s[12], s[13]), tmef = fmaxf(s[14], s[15]);
            float tm = fmaxf(fmaxf(fmaxf(tm01, tm23), fmaxf(tm45, tm67)),
                             fmaxf(fmaxf(tm89, tmab), fmaxf(tmcd, tmef)));
            float mn = fmaxf(m, tm);
            float corr = __expf(m - mn);  // exp(-inf)=0 on first tile
            m = mn;
            l *= corr;
            u64 cc = f2u2(corr, corr);
#pragma unroll
            for (int i = 0; i < 8; i++) acc[i] = fmul2(acc[i], cc);

            const ulonglong2* vrow = &sV[sub * 16][h * 4];
#pragma unroll
            for (int kk = 0; kk < 16; kk++) {
                float p = __expf(s[kk] - m);
                l += p;
                u64 pp = f2u2(p, p);
                const ulonglong2* vr = vrow + kk * 16;
                ulonglong2 va = vr[0], vb = vr[1], vc = vr[2], vd = vr[3];
                acc[0] = ffma2(pp, va.x, acc[0]);
                acc[1] = ffma2(pp, va.y, acc[1]);
                acc[2] = ffma2(pp, vb.x, acc[2]);
                acc[3] = ffma2(pp, vb.y, acc[3]);
                acc[4] = ffma2(pp, vc.x, acc[4]);
                acc[5] = ffma2(pp, vc.y, acc[5]);
                acc[6] = ffma2(pp, vd.x, acc[6]);
                acc[7] = ffma2(pp, vd.y, acc[7]);
            }
        }
        __syncthreads();
    }
    int row = blockIdx.y * (Nq * 4) + q * 4 + h;
    float* pp = part + (size_t)row * 18;
    pp[0] = m;
    pp[1] = l;
#pragma unroll
    for (int i = 0; i < 8; i++) {
        float2 f = u2f2(acc[i]);
        pp[2 + i * 2] = f.x;
        pp[3 + i * 2] = f.y;
    }
}

// ---------------- combine partials + residual + layernorm ----------------
__global__ void combine_ln(const float* __restrict__ part, int S, int Nq,
                           const float* __restrict__ hres, const float* __restrict__ g,
                           const float* __restrict__ b, float* __restrict__ out) {
    __shared__ float red[D];
    __shared__ float red2[D];
    int q = blockIdx.x;
    int d = threadIdx.x;
    int h = d >> 4;
    int i = d & 15;
    int rowbase = q * 4 + h;

    float M = -CUDART_INF_F;
    for (int s = 0; s < S; s++) M = fmaxf(M, part[(size_t)(s * Nq * 4 + rowbase) * 18]);
    float num = 0.f, den = 0.f;
    for (int s = 0; s < S; s++) {
        const float* pp = part + (size_t)(s * Nq * 4 + rowbase) * 18;
        float e = __expf(pp[0] - M);
        den += e * pp[1];
        num += e * pp[2 + i];
    }
    float val = num / den + hres[(size_t)q * D + d];

    red[d] = val;
    red2[d] = val * val;
    __syncthreads();
    for (int off = 32; off >= 1; off >>= 1) {
        if (d < off) {
            red[d] += red[d + off];
            red2[d] += red2[d + off];
        }
        __syncthreads();
    }
    float mu = red[0] * (1.f / 64.f);
    float var = red2[0] * (1.f / 64.f) - mu * mu;
    float r = rsqrtf(var + 1e-5f);
    out[(size_t)q * D + d] = (val - mu) * r * g[d] + b[d];
}

// ---------------- launch ----------------
extern "C" void kernel_launch(void* const* d_in, const int* in_sizes, int n_in,
                              void* d_out, int out_size) {
    const float* x_mol = (const float*)d_in[0];
    const int* ei_mol = (const int*)d_in[1];
    const float* ea_mol = (const float*)d_in[2];
    const float* x_prot = (const float*)d_in[3];
    const int* ei_prot = (const int*)d_in[4];
    const float* ea_prot = (const float*)d_in[5];
    const float* mol_w1 = (const float*)d_in[6];
    const float* mol_b1 = (const float*)d_in[7];
    const float* mol_w2 = (const float*)d_in[8];
    const float* mol_b2 = (const float*)d_in[9];
    const float* prot_w1 = (const float*)d_in[10];
    const float* prot_b1 = (const float*)d_in[11];
    const float* prot_w2 = (const float*)d_in[12];
    const float* prot_b2 = (const float*)d_in[13];
    const float* mp_wq = (const float*)d_in[14];
    const float* mp_bq = (const float*)d_in[15];
    const float* mp_wk = (const float*)d_in[16];
    const float* mp_bk = (const float*)d_in[17];
    const float* mp_wv = (const float*)d_in[18];
    const float* mp_bv = (const float*)d_in[19];
    const float* pm_wq = (const float*)d_in[20];
    const float* pm_bq = (const float*)d_in[21];
    const float* pm_wk = (const float*)d_in[22];
    const float* pm_bk = (const float*)d_in[23];
    const float* pm_wv = (const float*)d_in[24];
    const float* pm_bv = (const float*)d_in[25];
    const float* ln_mol_g = (const float*)d_in[26];
    const float* ln_mol_b = (const float*)d_in[27];
    const float* ln_prot_g = (const float*)d_in[28];
    const float* ln_prot_b = (const float*)d_in[29];

    int E_mol = in_sizes[1] / 2;
    int E_prot = in_sizes[4] / 2;
    float* out = (float*)d_out;

    float *aggr_mol, *cnt_mol, *aggr_prot, *cnt_prot;
    float *hmol, *hprot, *Qm, *Km, *Vm, *Qp, *Kp, *Vp, *part_mol, *part_prot;
    cudaGetSymbolAddress((void**)&aggr_mol, g_aggr_mol);
    cudaGetSymbolAddress((void**)&cnt_mol, g_cnt_mol);
    cudaGetSymbolAddress((void**)&aggr_prot, g_aggr_prot);
    cudaGetSymbolAddress((void**)&cnt_prot, g_cnt_prot);
    cudaGetSymbolAddress((void**)&hmol, g_hmol);
    cudaGetSymbolAddress((void**)&hprot, g_hprot);
    cudaGetSymbolAddress((void**)&Qm, g_Qm);
    cudaGetSymbolAddress((void**)&Km, g_Km);
    cudaGetSymbolAddress((void**)&Vm, g_Vm);
    cudaGetSymbolAddress((void**)&Qp, g_Qp);
    cudaGetSymbolAddress((void**)&Kp, g_Kp);
    cudaGetSymbolAddress((void**)&Vp, g_Vp);
    cudaGetSymbolAddress((void**)&part_mol, g_part_mol);
    cudaGetSymbolAddress((void**)&part_prot, g_part_prot);

    zero_all<<<256, 256>>>();

    edge_scatter<<<(E_mol * 16 + 255) / 256, 256>>>(x_mol, ei_mol, ea_mol, aggr_mol, cnt_mol, E_mol);
    edge_scatter<<<(E_prot * 16 + 255) / 256, 256>>>(x_prot, ei_prot, ea_prot, aggr_prot, cnt_prot, E_prot);

    gine_update_proj<<<NM / 4, 256>>>(x_mol, aggr_mol, cnt_mol, mol_w1, mol_b1, mol_w2, mol_b2,
                                      mp_wq, mp_bq, pm_wk, pm_bk, pm_wv, pm_bv, hmol, Qm, Km, Vm);
    gine_update_proj<<<NP / 4, 256>>>(x_prot, aggr_prot, cnt_prot, prot_w1, prot_b1, prot_w2, prot_b2,
                                      pm_wq, pm_bq, mp_wk, mp_bk, mp_wv, mp_bv, hprot, Qp, Kp, Vp);

    attn_partial<<<dim3(NM / 64, SPLIT_M), 256>>>(Qm, Kp, Vp, NM, NP / SPLIT_M, part_mol);
    attn_partial<<<dim3(NP / 64, SPLIT_P), 256>>>(Qp, Km, Vm, NP, NM / SPLIT_P, part_prot);

    combine_ln<<<NM, 64>>>(part_mol, SPLIT_M, NM, hmol, ln_mol_g, ln_mol_b, out);
    combine_ln<<<NP, 64>>>(part_prot, SPLIT_P, NP, hprot, ln_prot_g, ln_prot_b, out + NM * D);
}

// round 4
// speedup vs baseline: 2.0117x; 1.9306x over previous
#include <cuda_runtime.h>
#include <math_constants.h>

#define D 64
#define NM 2048
#define NP 8192
#define SPLIT_M 32
#define SPLIT_P 8
#define CHUNK 256

typedef unsigned long long u64;

// ---------------- f32x2 packed helpers ----------------
__device__ __forceinline__ u64 f2u2(float lo, float hi) {
    u64 r; asm("mov.b64 %0,{%1,%2};" : "=l"(r) : "f"(lo), "f"(hi)); return r;
}
__device__ __forceinline__ float2 u2f2(u64 v) {
    float2 r; asm("mov.b64 {%0,%1},%2;" : "=f"(r.x), "=f"(r.y) : "l"(v)); return r;
}
__device__ __forceinline__ u64 ffma2(u64 a, u64 b, u64 c) {
    u64 d; asm("fma.rn.f32x2 %0,%1,%2,%3;" : "=l"(d) : "l"(a), "l"(b), "l"(c)); return d;
}
__device__ __forceinline__ u64 fmul2(u64 a, u64 b) {
    u64 d; asm("mul.rn.f32x2 %0,%1,%2;" : "=l"(d) : "l"(a), "l"(b)); return d;
}
__device__ __forceinline__ u64 fadd2(u64 a, u64 b) {
    u64 d; asm("add.rn.f32x2 %0,%1,%2;" : "=l"(d) : "l"(a), "l"(b)); return d;
}

// bijective 16B-column permutation: identity on cols 0-7, rotate cols 8-15 by +2.
// Per-instruction column set {i,4+i,8+i,12+i} -> distinct mod 8 => conflict-free.
__device__ __forceinline__ int permc(int c) {
    return (c & 8) | ((c + ((c >> 2) & 2)) & 7);
}

// ---------------- device scratch ----------------
__device__ float g_aggr_mol[NM * D];
__device__ float g_cnt_mol[NM];
__device__ float g_aggr_prot[NP * D];
__device__ float g_cnt_prot[NP];
__device__ float g_hmol[NM * D];
__device__ float g_hprot[NP * D];
__device__ float g_Qm[NM * D], g_Km[NM * D], g_Vm[NM * D];
__device__ float g_Qp[NP * D], g_Kp[NP * D], g_Vp[NP * D];
__device__ float g_part_mol[SPLIT_M * NM * 4 * 18];
__device__ float g_part_prot[SPLIT_P * NP * 4 * 18];

// ---------------- zero accumulators ----------------
__global__ void zero_all() {
    int i = blockIdx.x * blockDim.x + threadIdx.x;
    int stride = gridDim.x * blockDim.x;
    float4 z = make_float4(0.f, 0.f, 0.f, 0.f);
    for (int j = i; j < NM * D / 4; j += stride) ((float4*)g_aggr_mol)[j] = z;
    for (int j = i; j < NP * D / 4; j += stride) ((float4*)g_aggr_prot)[j] = z;
    for (int j = i; j < NM; j += stride) g_cnt_mol[j] = 0.f;
    for (int j = i; j < NP; j += stride) g_cnt_prot[j] = 0.f;
}

// ---------------- GINE edge message + scatter-mean (vector RED) ----------------
__global__ void edge_scatter(const float* __restrict__ x, const int* __restrict__ ei,
                             const float* __restrict__ ea, float* __restrict__ aggr,
                             float* __restrict__ cnt, int E) {
    int idx = blockIdx.x * blockDim.x + threadIdx.x;
    if (idx >= E * 16) return;
    int e = idx >> 4;
    int c = idx & 15;
    int src = ei[e];
    int dst = ei[E + e];
    float4 xv = __ldg((const float4*)(x + (size_t)src * D) + c);
    float4 ev = __ldg((const float4*)(ea + (size_t)e * D) + c);
    float mx = fmaxf(xv.x + ev.x, 0.f);
    float my = fmaxf(xv.y + ev.y, 0.f);
    float mz = fmaxf(xv.z + ev.z, 0.f);
    float mw = fmaxf(xv.w + ev.w, 0.f);
    float* a = aggr + (size_t)dst * D + c * 4;
    asm volatile("red.global.v4.f32.add [%0], {%1,%2,%3,%4};"
                 :: "l"(a), "f"(mx), "f"(my), "f"(mz), "f"(mw) : "memory");
    if (c == 0)
        asm volatile("red.global.add.f32 [%0], %1;" :: "l"(&cnt[dst]), "f"(1.0f) : "memory");
}

// ---------------- GINE node update + QKV projection: warp-per-node ----------------
__global__ __launch_bounds__(256) void gine_update_proj(
    const float* __restrict__ x, const float* __restrict__ aggr,
    const float* __restrict__ cnt,
    const float* __restrict__ w1, const float* __restrict__ b1,
    const float* __restrict__ w2, const float* __restrict__ b2,
    const float* __restrict__ wq, const float* __restrict__ bq,
    const float* __restrict__ wk, const float* __restrict__ bk,
    const float* __restrict__ wv, const float* __restrict__ bv,
    float* __restrict__ h_out, float* __restrict__ Qo,
    float* __restrict__ Ko, float* __restrict__ Vo) {
    __shared__ float sv[8][D];
    int w = threadIdx.x >> 5;
    int lane = threadIdx.x & 31;
    int n = blockIdx.x * 8 + w;
    int j = lane * 2;
    float inv = 1.f / fmaxf(cnt[n], 1.f);
    float2 xv = *(const float2*)(x + (size_t)n * D + j);
    float2 av = *(const float2*)(aggr + (size_t)n * D + j);
    sv[w][j] = fmaf(av.x, inv, xv.x);
    sv[w][j + 1] = fmaf(av.y, inv, xv.y);
    __syncwarp();

    float2 bb = __ldg((const float2*)(b1 + j));
    float a0 = bb.x, a1 = bb.y, a2 = 0.f, a3 = 0.f;
#pragma unroll
    for (int i = 0; i < D; i += 2) {
        float t0 = sv[w][i], t1 = sv[w][i + 1];
        float2 w0 = __ldg((const float2*)(w1 + i * D + j));
        float2 w1v = __ldg((const float2*)(w1 + (i + 1) * D + j));
        a0 = fmaf(t0, w0.x, a0);
        a1 = fmaf(t0, w0.y, a1);
        a2 = fmaf(t1, w1v.x, a2);
        a3 = fmaf(t1, w1v.y, a3);
    }
    float r0 = fmaxf(a0 + a2, 0.f), r1 = fmaxf(a1 + a3, 0.f);
    __syncwarp();
    sv[w][j] = r0;
    sv[w][j + 1] = r1;
    __syncwarp();

    bb = __ldg((const float2*)(b2 + j));
    a0 = bb.x; a1 = bb.y; a2 = 0.f; a3 = 0.f;
#pragma unroll
    for (int i = 0; i < D; i += 2) {
        float t0 = sv[w][i], t1 = sv[w][i + 1];
        float2 w0 = __ldg((const float2*)(w2 + i * D + j));
        float2 w1v = __ldg((const float2*)(w2 + (i + 1) * D + j));
        a0 = fmaf(t0, w0.x, a0);
        a1 = fmaf(t0, w0.y, a1);
        a2 = fmaf(t1, w1v.x, a2);
        a3 = fmaf(t1, w1v.y, a3);
    }
    float h0 = fmaxf(a0 + a2, 0.f), h1 = fmaxf(a1 + a3, 0.f);
    *(float2*)(h_out + (size_t)n * D + j) = make_float2(h0, h1);
    __syncwarp();
    sv[w][j] = h0;
    sv[w][j + 1] = h1;
    __syncwarp();

    float2 bq2 = __ldg((const float2*)(bq + j));
    float2 bk2 = __ldg((const float2*)(bk + j));
    float2 bv2 = __ldg((const float2*)(bv + j));
    float q0 = bq2.x, q1 = bq2.y, k0 = bk2.x, k1 = bk2.y, v0 = bv2.x, v1 = bv2.y;
#pragma unroll
    for (int i = 0; i < D; i++) {
        float t = sv[w][i];
        float2 wqv = __ldg((const float2*)(wq + i * D + j));
        float2 wkv = __ldg((const float2*)(wk + i * D + j));
        float2 wvv = __ldg((const float2*)(wv + i * D + j));
        q0 = fmaf(t, wqv.x, q0);
        q1 = fmaf(t, wqv.y, q1);
        k0 = fmaf(t, wkv.x, k0);
        k1 = fmaf(t, wkv.y, k1);
        v0 = fmaf(t, wvv.x, v0);
        v1 = fmaf(t, wvv.y, v1);
    }
    *(float2*)(Qo + (size_t)n * D + j) = make_float2(q0, q1);
    *(float2*)(Ko + (size_t)n * D + j) = make_float2(k0, k1);
    *(float2*)(Vo + (size_t)n * D + j) = make_float2(v0, v1);
}

// ---------------- unified split-K flash attention ----------------
// 2048 uniform tiles: 64 queries x 256 keys. Tiles 0..1023 = mol->prot, 1024..2047 = prot->mol.
__global__ __launch_bounds__(256, 2) void attn_all(
    const float* __restrict__ Qm, const float* __restrict__ Kp, const float* __restrict__ Vp,
    float* __restrict__ partM,
    const float* __restrict__ Qp, const float* __restrict__ Km, const float* __restrict__ Vm,
    float* __restrict__ partP) {
    __shared__ ulonglong2 sK[64 * 16];
    __shared__ ulonglong2 sV[64 * 16];
    int b = blockIdx.x;
    const float *Q, *K, *V;
    float* part;
    int Nq, qt, sp;
    if (b < 1024) {
        Q = Qm; K = Kp; V = Vp; part = partM; Nq = NM;
        qt = b >> 5; sp = b & 31;
    } else {
        int b2 = b - 1024;
        Q = Qp; K = Km; V = Vm; part = partP; Nq = NP;
        qt = b2 >> 3; sp = b2 & 7;
    }
    int t = threadIdx.x;
    int ql = t >> 2;
    int h = t & 3;
    int q = qt * 64 + ql;
    int k0 = sp * CHUNK;

    int pc[4];
#pragma unroll
    for (int i = 0; i < 4; i++) pc[i] = permc(h * 4 + i);

    u64 qp[8];
    {
        const float4* Qv = (const float4*)(Q + (size_t)q * D + h * 16);
#pragma unroll
        for (int r = 0; r < 4; r++) {
            float4 v = Qv[r];
            qp[r * 2 + 0] = f2u2(v.x * 0.25f, v.y * 0.25f);
            qp[r * 2 + 1] = f2u2(v.z * 0.25f, v.w * 0.25f);
        }
    }

    float m = -CUDART_INF_F;
    float l = 0.f;
    u64 acc[8];
#pragma unroll
    for (int i = 0; i < 8; i++) acc[i] = 0ull;

    for (int kt = 0; kt < CHUNK; kt += 64) {
        const ulonglong2* Kg = (const ulonglong2*)(K + (size_t)(k0 + kt) * D);
        const ulonglong2* Vg = (const ulonglong2*)(V + (size_t)(k0 + kt) * D);
#pragma unroll
        for (int r = 0; r < 4; r++) {
            int idx = t + r * 256;
            int row = idx >> 4;
            int col = idx & 15;
            int p = permc(col);
            sK[row * 16 + p] = Kg[idx];
            sV[row * 16 + p] = Vg[idx];
        }
        __syncthreads();

        for (int sub = 0; sub < 8; sub++) {
            float s[8];
#pragma unroll
            for (int kk = 0; kk < 8; kk++) {
                int key = sub * 8 + kk;
                ulonglong2 ka = sK[key * 16 + pc[0]];
                ulonglong2 kb = sK[key * 16 + pc[1]];
                ulonglong2 kc = sK[key * 16 + pc[2]];
                ulonglong2 kd = sK[key * 16 + pc[3]];
                u64 sa = fmul2(qp[0], ka.x);
                u64 sb = fmul2(qp[1], ka.y);
                sa = ffma2(qp[2], kb.x, sa);
                sb = ffma2(qp[3], kb.y, sb);
                sa = ffma2(qp[4], kc.x, sa);
                sb = ffma2(qp[5], kc.y, sb);
                sa = ffma2(qp[6], kd.x, sa);
                sb = ffma2(qp[7], kd.y, sb);
                float2 f = u2f2(fadd2(sa, sb));
                s[kk] = f.x + f.y;
            }
            float t01 = fmaxf(s[0], s[1]), t23 = fmaxf(s[2], s[3]);
            float t45 = fmaxf(s[4], s[5]), t67 = fmaxf(s[6], s[7]);
            float tm = fmaxf(fmaxf(t01, t23), fmaxf(t45, t67));
            float mn = fmaxf(m, tm);
            float corr = __expf(m - mn);  // exp(-inf)=0 on first tile
            m = mn;
            l *= corr;
            u64 cc = f2u2(corr, corr);
#pragma unroll
            for (int i = 0; i < 8; i++) acc[i] = fmul2(acc[i], cc);

#pragma unroll
            for (int kk = 0; kk < 8; kk++) {
                int key = sub * 8 + kk;
                float p = __expf(s[kk] - m);
                l += p;
                u64 pp = f2u2(p, p);
                ulonglong2 va = sV[key * 16 + pc[0]];
                ulonglong2 vb = sV[key * 16 + pc[1]];
                ulonglong2 vc = sV[key * 16 + pc[2]];
                ulonglong2 vd = sV[key * 16 + pc[3]];
                acc[0] = ffma2(pp, va.x, acc[0]);
                acc[1] = ffma2(pp, va.y, acc[1]);
                acc[2] = ffma2(pp, vb.x, acc[2]);
                acc[3] = ffma2(pp, vb.y, acc[3]);
                acc[4] = ffma2(pp, vc.x, acc[4]);
                acc[5] = ffma2(pp, vc.y, acc[5]);
                acc[6] = ffma2(pp, vd.x, acc[6]);
                acc[7] = ffma2(pp, vd.y, acc[7]);
            }
        }
        __syncthreads();
    }
    int row = sp * (Nq * 4) + q * 4 + h;
    float* pw = part + (size_t)row * 18;
    pw[0] = m;
    pw[1] = l;
#pragma unroll
    for (int i = 0; i < 8; i++) {
        float2 f = u2f2(acc[i]);
        pw[2 + i * 2] = f.x;
        pw[3 + i * 2] = f.y;
    }
}

// ---------------- combine partials + residual + layernorm ----------------
__global__ void combine_ln(const float* __restrict__ part, int S, int Nq,
                           const float* __restrict__ hres, const float* __restrict__ g,
                           const float* __restrict__ b, float* __restrict__ out) {
    __shared__ float red[D];
    __shared__ float red2[D];
    int q = blockIdx.x;
    int d = threadIdx.x;
    int h = d >> 4;
    int i = d & 15;
    int rowbase = q * 4 + h;

    float M = -CUDART_INF_F;
    for (int s = 0; s < S; s++) M = fmaxf(M, part[(size_t)(s * Nq * 4 + rowbase) * 18]);
    float num = 0.f, den = 0.f;
    for (int s = 0; s < S; s++) {
        const float* pp = part + (size_t)(s * Nq * 4 + rowbase) * 18;
        float e = __expf(pp[0] - M);
        den += e * pp[1];
        num += e * pp[2 + i];
    }
    float val = num / den + hres[(size_t)q * D + d];

    red[d] = val;
    red2[d] = val * val;
    __syncthreads();
    for (int off = 32; off >= 1; off >>= 1) {
        if (d < off) {
            red[d] += red[d + off];
            red2[d] += red2[d + off];
        }
        __syncthreads();
    }
    float mu = red[0] * (1.f / 64.f);
    float var = red2[0] * (1.f / 64.f) - mu * mu;
    float r = rsqrtf(var + 1e-5f);
    out[(size_t)q * D + d] = (val - mu) * r * g[d] + b[d];
}

// ---------------- launch ----------------
extern "C" void kernel_launch(void* const* d_in, const int* in_sizes, int n_in,
                              void* d_out, int out_size) {
    const float* x_mol = (const float*)d_in[0];
    const int* ei_mol = (const int*)d_in[1];
    const float* ea_mol = (const float*)d_in[2];
    const float* x_prot = (const float*)d_in[3];
    const int* ei_prot = (const int*)d_in[4];
    const float* ea_prot = (const float*)d_in[5];
    const float* mol_w1 = (const float*)d_in[6];
    const float* mol_b1 = (const float*)d_in[7];
    const float* mol_w2 = (const float*)d_in[8];
    const float* mol_b2 = (const float*)d_in[9];
    const float* prot_w1 = (const float*)d_in[10];
    const float* prot_b1 = (const float*)d_in[11];
    const float* prot_w2 = (const float*)d_in[12];
    const float* prot_b2 = (const float*)d_in[13];
    const float* mp_wq = (const float*)d_in[14];
    const float* mp_bq = (const float*)d_in[15];
    const float* mp_wk = (const float*)d_in[16];
    const float* mp_bk = (const float*)d_in[17];
    const float* mp_wv = (const float*)d_in[18];
    const float* mp_bv = (const float*)d_in[19];
    const float* pm_wq = (const float*)d_in[20];
    const float* pm_bq = (const float*)d_in[21];
    const float* pm_wk = (const float*)d_in[22];
    const float* pm_bk = (const float*)d_in[23];
    const float* pm_wv = (const float*)d_in[24];
    const float* pm_bv = (const float*)d_in[25];
    const float* ln_mol_g = (const float*)d_in[26];
    const float* ln_mol_b = (const float*)d_in[27];
    const float* ln_prot_g = (const float*)d_in[28];
    const float* ln_prot_b = (const float*)d_in[29];

    int E_mol = in_sizes[1] / 2;
    int E_prot = in_sizes[4] / 2;
    float* out = (float*)d_out;

    float *aggr_mol, *cnt_mol, *aggr_prot, *cnt_prot;
    float *hmol, *hprot, *Qm, *Km, *Vm, *Qp, *Kp, *Vp, *part_mol, *part_prot;
    cudaGetSymbolAddress((void**)&aggr_mol, g_aggr_mol);
    cudaGetSymbolAddress((void**)&cnt_mol, g_cnt_mol);
    cudaGetSymbolAddress((void**)&aggr_prot, g_aggr_prot);
    cudaGetSymbolAddress((void**)&cnt_prot, g_cnt_prot);
    cudaGetSymbolAddress((void**)&hmol, g_hmol);
    cudaGetSymbolAddress((void**)&hprot, g_hprot);
    cudaGetSymbolAddress((void**)&Qm, g_Qm);
    cudaGetSymbolAddress((void**)&Km, g_Km);
    cudaGetSymbolAddress((void**)&Vm, g_Vm);
    cudaGetSymbolAddress((void**)&Qp, g_Qp);
    cudaGetSymbolAddress((void**)&Kp, g_Kp);
    cudaGetSymbolAddress((void**)&Vp, g_Vp);
    cudaGetSymbolAddress((void**)&part_mol, g_part_mol);
    cudaGetSymbolAddress((void**)&part_prot, g_part_prot);

    zero_all<<<256, 256>>>();

    edge_scatter<<<(E_mol * 16 + 255) / 256, 256>>>(x_mol, ei_mol, ea_mol, aggr_mol, cnt_mol, E_mol);
    edge_scatter<<<(E_prot * 16 + 255) / 256, 256>>>(x_prot, ei_prot, ea_prot, aggr_prot, cnt_prot, E_prot);

    gine_update_proj<<<NM / 8, 256>>>(x_mol, aggr_mol, cnt_mol, mol_w1, mol_b1, mol_w2, mol_b2,
                                      mp_wq, mp_bq, pm_wk, pm_bk, pm_wv, pm_bv, hmol, Qm, Km, Vm);
    gine_update_proj<<<NP / 8, 256>>>(x_prot, aggr_prot, cnt_prot, prot_w1, prot_b1, prot_w2, prot_b2,
                                      pm_wq, pm_bq, mp_wk, mp_bk, mp_wv, mp_bv, hprot, Qp, Kp, Vp);

    attn_all<<<2048, 256>>>(Qm, Kp, Vp, part_mol, Qp, Km, Vm, part_prot);

    combine_ln<<<NM, 64>>>(part_mol, SPLIT_M, NM, hmol, ln_mol_g, ln_mol_b, out);
    combine_ln<<<NP, 64>>>(part_prot, SPLIT_P, NP, hprot, ln_prot_g, ln_prot_b, out + NM * D);
}

// round 5
// speedup vs baseline: 2.0263x; 1.0073x over previous
#include <cuda_runtime.h>
#include <math_constants.h>

#define D 64
#define NM 2048
#define NP 8192
#define SPLIT_M 32
#define SPLIT_P 8
#define CHUNK 256

typedef unsigned long long u64;

// ---------------- f32x2 packed helpers ----------------
__device__ __forceinline__ u64 f2u2(float lo, float hi) {
    u64 r; asm("mov.b64 %0,{%1,%2};" : "=l"(r) : "f"(lo), "f"(hi)); return r;
}
__device__ __forceinline__ float2 u2f2(u64 v) {
    float2 r; asm("mov.b64 {%0,%1},%2;" : "=f"(r.x), "=f"(r.y) : "l"(v)); return r;
}
__device__ __forceinline__ u64 ffma2(u64 a, u64 b, u64 c) {
    u64 d; asm("fma.rn.f32x2 %0,%1,%2,%3;" : "=l"(d) : "l"(a), "l"(b), "l"(c)); return d;
}
__device__ __forceinline__ u64 fmul2(u64 a, u64 b) {
    u64 d; asm("mul.rn.f32x2 %0,%1,%2;" : "=l"(d) : "l"(a), "l"(b)); return d;
}
__device__ __forceinline__ u64 fadd2(u64 a, u64 b) {
    u64 d; asm("add.rn.f32x2 %0,%1,%2;" : "=l"(d) : "l"(a), "l"(b)); return d;
}

// bijective 16B-column permutation: identity on cols 0-7, rotate cols 8-15 by +2.
__device__ __forceinline__ int permc(int c) {
    return (c & 8) | ((c + ((c >> 2) & 2)) & 7);
}

__device__ __forceinline__ unsigned smem_u32(const void* p) {
    unsigned r;
    asm("{.reg .u64 t; cvta.to.shared.u64 t, %1; cvt.u32.u64 %0, t;}" : "=r"(r) : "l"(p));
    return r;
}

// ---------------- device scratch ----------------
__device__ float g_aggr_mol[NM * D];
__device__ float g_cnt_mol[NM];
__device__ float g_aggr_prot[NP * D];
__device__ float g_cnt_prot[NP];
__device__ float g_hmol[NM * D];
__device__ float g_hprot[NP * D];
__device__ float g_Qm[NM * D], g_Km[NM * D], g_Vm[NM * D];
__device__ float g_Qp[NP * D], g_Kp[NP * D], g_Vp[NP * D];
__device__ float g_part_mol[SPLIT_M * NM * 4 * 18];
__device__ float g_part_prot[SPLIT_P * NP * 4 * 18];

// ---------------- zero accumulators ----------------
__global__ void zero_all() {
    int i = blockIdx.x * blockDim.x + threadIdx.x;
    int stride = gridDim.x * blockDim.x;
    float4 z = make_float4(0.f, 0.f, 0.f, 0.f);
    for (int j = i; j < NM * D / 4; j += stride) ((float4*)g_aggr_mol)[j] = z;
    for (int j = i; j < NP * D / 4; j += stride) ((float4*)g_aggr_prot)[j] = z;
    for (int j = i; j < NM; j += stride) g_cnt_mol[j] = 0.f;
    for (int j = i; j < NP; j += stride) g_cnt_prot[j] = 0.f;
}

// ---------------- fused GINE edge scatter (both graphs, vector RED) ----------------
__global__ void edge_scatter_all(
    const float* __restrict__ xm, const int* __restrict__ eim, const float* __restrict__ eam,
    float* __restrict__ aggrm, float* __restrict__ cntm, int Em,
    const float* __restrict__ xp, const int* __restrict__ eip, const float* __restrict__ eap,
    float* __restrict__ aggrp, float* __restrict__ cntp, int Ep) {
    int idx = blockIdx.x * blockDim.x + threadIdx.x;
    const float* x;
    const int* ei;
    const float* ea;
    float* aggr;
    float* cnt;
    int E;
    if (idx < Em * 16) {
        x = xm; ei = eim; ea = eam; aggr = aggrm; cnt = cntm; E = Em;
    } else {
        idx -= Em * 16;
        if (idx >= Ep * 16) return;
        x = xp; ei = eip; ea = eap; aggr = aggrp; cnt = cntp; E = Ep;
    }
    int e = idx >> 4;
    int c = idx & 15;
    int src = ei[e];
    int dst = ei[E + e];
    float4 xv = __ldg((const float4*)(x + (size_t)src * D) + c);
    float4 ev = __ldg((const float4*)(ea + (size_t)e * D) + c);
    float mx = fmaxf(xv.x + ev.x, 0.f);
    float my = fmaxf(xv.y + ev.y, 0.f);
    float mz = fmaxf(xv.z + ev.z, 0.f);
    float mw = fmaxf(xv.w + ev.w, 0.f);
    float* a = aggr + (size_t)dst * D + c * 4;
    asm volatile("red.global.v4.f32.add [%0], {%1,%2,%3,%4};"
                 :: "l"(a), "f"(mx), "f"(my), "f"(mz), "f"(mw) : "memory");
    if (c == 0)
        asm volatile("red.global.add.f32 [%0], %1;" :: "l"(&cnt[dst]), "f"(1.0f) : "memory");
}

// ---------------- fused GINE node update + QKV projection (both node sets) ----------------
__global__ __launch_bounds__(256) void gine_all(
    const float* __restrict__ xm, const float* __restrict__ aggrm, const float* __restrict__ cntm,
    const float* __restrict__ mw1, const float* __restrict__ mb1,
    const float* __restrict__ mw2, const float* __restrict__ mb2,
    const float* __restrict__ mwq, const float* __restrict__ mbq,
    const float* __restrict__ mwk, const float* __restrict__ mbk,
    const float* __restrict__ mwv, const float* __restrict__ mbv,
    float* __restrict__ hm, float* __restrict__ Qm, float* __restrict__ Km, float* __restrict__ Vm,
    const float* __restrict__ xp, const float* __restrict__ aggrp, const float* __restrict__ cntp,
    const float* __restrict__ pw1, const float* __restrict__ pb1,
    const float* __restrict__ pw2, const float* __restrict__ pb2,
    const float* __restrict__ pwq, const float* __restrict__ pbq,
    const float* __restrict__ pwk, const float* __restrict__ pbk,
    const float* __restrict__ pwv, const float* __restrict__ pbv,
    float* __restrict__ hp, float* __restrict__ Qp, float* __restrict__ Kp, float* __restrict__ Vp) {
    const float *x, *aggr, *cnt, *w1, *b1, *w2, *b2, *wq, *bq, *wk, *bk, *wv, *bv;
    float *h_out, *Qo, *Ko, *Vo;
    int nb = blockIdx.x;
    if (nb < NM / 8) {
        x = xm; aggr = aggrm; cnt = cntm;
        w1 = mw1; b1 = mb1; w2 = mw2; b2 = mb2;
        wq = mwq; bq = mbq; wk = mwk; bk = mbk; wv = mwv; bv = mbv;
        h_out = hm; Qo = Qm; Ko = Km; Vo = Vm;
    } else {
        nb -= NM / 8;
        x = xp; aggr = aggrp; cnt = cntp;
        w1 = pw1; b1 = pb1; w2 = pw2; b2 = pb2;
        wq = pwq; bq = pbq; wk = pwk; bk = pbk; wv = pwv; bv = pbv;
        h_out = hp; Qo = Qp; Ko = Kp; Vo = Vp;
    }
    __shared__ float sv[8][D];
    int w = threadIdx.x >> 5;
    int lane = threadIdx.x & 31;
    int n = nb * 8 + w;
    int j = lane * 2;
    float inv = 1.f / fmaxf(cnt[n], 1.f);
    float2 xv = *(const float2*)(x + (size_t)n * D + j);
    float2 av = *(const float2*)(aggr + (size_t)n * D + j);
    sv[w][j] = fmaf(av.x, inv, xv.x);
    sv[w][j + 1] = fmaf(av.y, inv, xv.y);
    __syncwarp();

    float2 bb = __ldg((const float2*)(b1 + j));
    float a0 = bb.x, a1 = bb.y, a2 = 0.f, a3 = 0.f;
#pragma unroll
    for (int i = 0; i < D; i += 2) {
        float t0 = sv[w][i], t1 = sv[w][i + 1];
        float2 w0 = __ldg((const float2*)(w1 + i * D + j));
        float2 w1v = __ldg((const float2*)(w1 + (i + 1) * D + j));
        a0 = fmaf(t0, w0.x, a0);
        a1 = fmaf(t0, w0.y, a1);
        a2 = fmaf(t1, w1v.x, a2);
        a3 = fmaf(t1, w1v.y, a3);
    }
    float r0 = fmaxf(a0 + a2, 0.f), r1 = fmaxf(a1 + a3, 0.f);
    __syncwarp();
    sv[w][j] = r0;
    sv[w][j + 1] = r1;
    __syncwarp();

    bb = __ldg((const float2*)(b2 + j));
    a0 = bb.x; a1 = bb.y; a2 = 0.f; a3 = 0.f;
#pragma unroll
    for (int i = 0; i < D; i += 2) {
        float t0 = sv[w][i], t1 = sv[w][i + 1];
        float2 w0 = __ldg((const float2*)(w2 + i * D + j));
        float2 w1v = __ldg((const float2*)(w2 + (i + 1) * D + j));
        a0 = fmaf(t0, w0.x, a0);
        a1 = fmaf(t0, w0.y, a1);
        a2 = fmaf(t1, w1v.x, a2);
        a3 = fmaf(t1, w1v.y, a3);
    }
    float h0 = fmaxf(a0 + a2, 0.f), h1 = fmaxf(a1 + a3, 0.f);
    *(float2*)(h_out + (size_t)n * D + j) = make_float2(h0, h1);
    __syncwarp();
    sv[w][j] = h0;
    sv[w][j + 1] = h1;
    __syncwarp();

    float2 bq2 = __ldg((const float2*)(bq + j));
    float2 bk2 = __ldg((const float2*)(bk + j));
    float2 bv2 = __ldg((const float2*)(bv + j));
    float q0 = bq2.x, q1 = bq2.y, k0 = bk2.x, k1 = bk2.y, v0 = bv2.x, v1 = bv2.y;
#pragma unroll
    for (int i = 0; i < D; i++) {
        float t = sv[w][i];
        float2 wqv = __ldg((const float2*)(wq + i * D + j));
        float2 wkv = __ldg((const float2*)(wk + i * D + j));
        float2 wvv = __ldg((const float2*)(wv + i * D + j));
        q0 = fmaf(t, wqv.x, q0);
        q1 = fmaf(t, wqv.y, q1);
        k0 = fmaf(t, wkv.x, k0);
        k1 = fmaf(t, wkv.y, k1);
        v0 = fmaf(t, wvv.x, v0);
        v1 = fmaf(t, wvv.y, v1);
    }
    *(float2*)(Qo + (size_t)n * D + j) = make_float2(q0, q1);
    *(float2*)(Ko + (size_t)n * D + j) = make_float2(k0, k1);
    *(float2*)(Vo + (size_t)n * D + j) = make_float2(v0, v1);
}

// ---------------- unified split-K flash attention, cp.async double-buffered ----------------
// dynamic smem: K buffers [2][1024] ulonglong2, then V buffers [2][1024].
__global__ __launch_bounds__(256, 2) void attn_all(
    const float* __restrict__ Qm, const float* __restrict__ Kp, const float* __restrict__ Vp,
    float* __restrict__ partM,
    const float* __restrict__ Qp, const float* __restrict__ Km, const float* __restrict__ Vm,
    float* __restrict__ partP) {
    extern __shared__ ulonglong2 smem[];
    ulonglong2* sK = smem;          // [2][1024]
    ulonglong2* sV = smem + 2048;   // [2][1024]
    unsigned sK_u32 = smem_u32(sK);
    unsigned sV_u32 = smem_u32(sV);

    int b = blockIdx.x;
    const float *Q, *K, *V;
    float* part;
    int Nq, qt, sp;
    if (b < 1024) {
        Q = Qm; K = Kp; V = Vp; part = partM; Nq = NM;
        qt = b >> 5; sp = b & 31;
    } else {
        int b2 = b - 1024;
        Q = Qp; K = Km; V = Vm; part = partP; Nq = NP;
        qt = b2 >> 3; sp = b2 & 7;
    }
    int t = threadIdx.x;
    int ql = t >> 2;
    int h = t & 3;
    int q = qt * 64 + ql;
    int k0 = sp * CHUNK;

    int pc[4];
#pragma unroll
    for (int i = 0; i < 4; i++) pc[i] = permc(h * 4 + i);

    // per-thread smem dst offsets (permuted) for the 4 chunks it copies each tile
    unsigned dsts[4];
#pragma unroll
    for (int r = 0; r < 4; r++) {
        int idx = t + r * 256;
        int row = idx >> 4;
        int col = idx & 15;
        dsts[r] = (unsigned)((row * 16 + permc(col)) * 16);
    }

    u64 qp[8];
    {
        const float4* Qv = (const float4*)(Q + (size_t)q * D + h * 16);
#pragma unroll
        for (int r = 0; r < 4; r++) {
            float4 v = Qv[r];
            qp[r * 2 + 0] = f2u2(v.x * 0.25f, v.y * 0.25f);
            qp[r * 2 + 1] = f2u2(v.z * 0.25f, v.w * 0.25f);
        }
    }

    float m = -CUDART_INF_F;
    float l = 0.f;
    u64 acc[8];
#pragma unroll
    for (int i = 0; i < 8; i++) acc[i] = 0ull;

    // prefetch tile 0 into buffer 0
    {
        const char* Kg = (const char*)(K + (size_t)k0 * D);
        const char* Vg = (const char*)(V + (size_t)k0 * D);
#pragma unroll
        for (int r = 0; r < 4; r++) {
            int idx = t + r * 256;
            asm volatile("cp.async.cg.shared.global [%0], [%1], 16;"
                         :: "r"(sK_u32 + dsts[r]), "l"(Kg + idx * 16) : "memory");
            asm volatile("cp.async.cg.shared.global [%0], [%1], 16;"
                         :: "r"(sV_u32 + dsts[r]), "l"(Vg + idx * 16) : "memory");
        }
        asm volatile("cp.async.commit_group;" ::: "memory");
    }

#pragma unroll
    for (int tile = 0; tile < 4; tile++) {
        int buf = tile & 1;
        if (tile < 3) {
            int nbuf = (tile + 1) & 1;
            const char* Kg = (const char*)(K + (size_t)(k0 + (tile + 1) * 64) * D);
            const char* Vg = (const char*)(V + (size_t)(k0 + (tile + 1) * 64) * D);
            unsigned kb = sK_u32 + nbuf * 16384;
            unsigned vb = sV_u32 + nbuf * 16384;
#pragma unroll
            for (int r = 0; r < 4; r++) {
                int idx = t + r * 256;
                asm volatile("cp.async.cg.shared.global [%0], [%1], 16;"
                             :: "r"(kb + dsts[r]), "l"(Kg + idx * 16) : "memory");
                asm volatile("cp.async.cg.shared.global [%0], [%1], 16;"
                             :: "r"(vb + dsts[r]), "l"(Vg + idx * 16) : "memory");
            }
            asm volatile("cp.async.commit_group;" ::: "memory");
            asm volatile("cp.async.wait_group 1;" ::: "memory");
        } else {
            asm volatile("cp.async.wait_group 0;" ::: "memory");
        }
        __syncthreads();

        const ulonglong2* kbase = sK + buf * 1024;
        const ulonglong2* vbase = sV + buf * 1024;
        for (int sub = 0; sub < 8; sub++) {
            float s[8];
#pragma unroll
            for (int kk = 0; kk < 8; kk++) {
                int key = sub * 8 + kk;
                ulonglong2 ka = kbase[key * 16 + pc[0]];
                ulonglong2 kb2 = kbase[key * 16 + pc[1]];
                ulonglong2 kc = kbase[key * 16 + pc[2]];
                ulonglong2 kd = kbase[key * 16 + pc[3]];
                u64 sa = fmul2(qp[0], ka.x);
                u64 sb = fmul2(qp[1], ka.y);
                sa = ffma2(qp[2], kb2.x, sa);
                sb = ffma2(qp[3], kb2.y, sb);
                sa = ffma2(qp[4], kc.x, sa);
                sb = ffma2(qp[5], kc.y, sb);
                sa = ffma2(qp[6], kd.x, sa);
                sb = ffma2(qp[7], kd.y, sb);
                float2 f = u2f2(fadd2(sa, sb));
                s[kk] = f.x + f.y;
            }
            float t01 = fmaxf(s[0], s[1]), t23 = fmaxf(s[2], s[3]);
            float t45 = fmaxf(s[4], s[5]), t67 = fmaxf(s[6], s[7]);
            float tm = fmaxf(fmaxf(t01, t23), fmaxf(t45, t67));
            float mn = fmaxf(m, tm);
            float corr = __expf(m - mn);  // exp(-inf)=0 on first tile
            m = mn;
            l *= corr;
            u64 cc = f2u2(corr, corr);
#pragma unroll
            for (int i = 0; i < 8; i++) acc[i] = fmul2(acc[i], cc);

#pragma unroll
            for (int kk = 0; kk < 8; kk++) {
                int key = sub * 8 + kk;
                float p = __expf(s[kk] - m);
                l += p;
                u64 pp = f2u2(p, p);
                ulonglong2 va = vbase[key * 16 + pc[0]];
                ulonglong2 vb2 = vbase[key * 16 + pc[1]];
                ulonglong2 vc = vbase[key * 16 + pc[2]];
                ulonglong2 vd = vbase[key * 16 + pc[3]];
                acc[0] = ffma2(pp, va.x, acc[0]);
                acc[1] = ffma2(pp, va.y, acc[1]);
                acc[2] = ffma2(pp, vb2.x, acc[2]);
                acc[3] = ffma2(pp, vb2.y, acc[3]);
                acc[4] = ffma2(pp, vc.x, acc[4]);
                acc[5] = ffma2(pp, vc.y, acc[5]);
                acc[6] = ffma2(pp, vd.x, acc[6]);
                acc[7] = ffma2(pp, vd.y, acc[7]);
            }
        }
        __syncthreads();
    }
    int row = sp * (Nq * 4) + q * 4 + h;
    float* pw = part + (size_t)row * 18;
    pw[0] = m;
    pw[1] = l;
#pragma unroll
    for (int i = 0; i < 8; i++) {
        float2 f = u2f2(acc[i]);
        pw[2 + i * 2] = f.x;
        pw[3 + i * 2] = f.y;
    }
}

// ---------------- combine partials + residual + layernorm ----------------
__global__ void combine_ln(const float* __restrict__ part, int S, int Nq,
                           const float* __restrict__ hres, const float* __restrict__ g,
                           const float* __restrict__ b, float* __restrict__ out) {
    __shared__ float red[D];
    __shared__ float red2[D];
    int q = blockIdx.x;
    int d = threadIdx.x;
    int h = d >> 4;
    int i = d & 15;
    int rowbase = q * 4 + h;

    float M = -CUDART_INF_F;
    for (int s = 0; s < S; s++) M = fmaxf(M, part[(size_t)(s * Nq * 4 + rowbase) * 18]);
    float num = 0.f, den = 0.f;
    for (int s = 0; s < S; s++) {
        const float* pp = part + (size_t)(s * Nq * 4 + rowbase) * 18;
        float e = __expf(pp[0] - M);
        den += e * pp[1];
        num += e * pp[2 + i];
    }
    float val = num / den + hres[(size_t)q * D + d];

    red[d] = val;
    red2[d] = val * val;
    __syncthreads();
    for (int off = 32; off >= 1; off >>= 1) {
        if (d < off) {
            red[d] += red[d + off];
            red2[d] += red2[d + off];
        }
        __syncthreads();
    }
    float mu = red[0] * (1.f / 64.f);
    float var = red2[0] * (1.f / 64.f) - mu * mu;
    float r = rsqrtf(var + 1e-5f);
    out[(size_t)q * D + d] = (val - mu) * r * g[d] + b[d];
}

// ---------------- launch ----------------
extern "C" void kernel_launch(void* const* d_in, const int* in_sizes, int n_in,
                              void* d_out, int out_size) {
    const float* x_mol = (const float*)d_in[0];
    const int* ei_mol = (const int*)d_in[1];
    const float* ea_mol = (const float*)d_in[2];
    const float* x_prot = (const float*)d_in[3];
    const int* ei_prot = (const int*)d_in[4];
    const float* ea_prot = (const float*)d_in[5];
    const float* mol_w1 = (const float*)d_in[6];
    const float* mol_b1 = (const float*)d_in[7];
    const float* mol_w2 = (const float*)d_in[8];
    const float* mol_b2 = (const float*)d_in[9];
    const float* prot_w1 = (const float*)d_in[10];
    const float* prot_b1 = (const float*)d_in[11];
    const float* prot_w2 = (const float*)d_in[12];
    const float* prot_b2 = (const float*)d_in[13];
    const float* mp_wq = (const float*)d_in[14];
    const float* mp_bq = (const float*)d_in[15];
    const float* mp_wk = (const float*)d_in[16];
    const float* mp_bk = (const float*)d_in[17];
    const float* mp_wv = (const float*)d_in[18];
    const float* mp_bv = (const float*)d_in[19];
    const float* pm_wq = (const float*)d_in[20];
    const float* pm_bq = (const float*)d_in[21];
    const float* pm_wk = (const float*)d_in[22];
    const float* pm_bk = (const float*)d_in[23];
    const float* pm_wv = (const float*)d_in[24];
    const float* pm_bv = (const float*)d_in[25];
    const float* ln_mol_g = (const float*)d_in[26];
    const float* ln_mol_b = (const float*)d_in[27];
    const float* ln_prot_g = (const float*)d_in[28];
    const float* ln_prot_b = (const float*)d_in[29];

    int E_mol = in_sizes[1] / 2;
    int E_prot = in_sizes[4] / 2;
    float* out = (float*)d_out;

    float *aggr_mol, *cnt_mol, *aggr_prot, *cnt_prot;
    float *hmol, *hprot, *Qm, *Km, *Vm, *Qp, *Kp, *Vp, *part_mol, *part_prot;
    cudaGetSymbolAddress((void**)&aggr_mol, g_aggr_mol);
    cudaGetSymbolAddress((void**)&cnt_mol, g_cnt_mol);
    cudaGetSymbolAddress((void**)&aggr_prot, g_aggr_prot);
    cudaGetSymbolAddress((void**)&cnt_prot, g_cnt_prot);
    cudaGetSymbolAddress((void**)&hmol, g_hmol);
    cudaGetSymbolAddress((void**)&hprot, g_hprot);
    cudaGetSymbolAddress((void**)&Qm, g_Qm);
    cudaGetSymbolAddress((void**)&Km, g_Km);
    cudaGetSymbolAddress((void**)&Vm, g_Vm);
    cudaGetSymbolAddress((void**)&Qp, g_Qp);
    cudaGetSymbolAddress((void**)&Kp, g_Kp);
    cudaGetSymbolAddress((void**)&Vp, g_Vp);
    cudaGetSymbolAddress((void**)&part_mol, g_part_mol);
    cudaGetSymbolAddress((void**)&part_prot, g_part_prot);

    static int smem_set = 0;
    if (!smem_set) {
        cudaFuncSetAttribute(attn_all, cudaFuncAttributeMaxDynamicSharedMemorySize, 65536);
        smem_set = 1;
    }

    zero_all<<<256, 256>>>();

    int total_scatter = (E_mol + E_prot) * 16;
    edge_scatter_all<<<(total_scatter + 255) / 256, 256>>>(
        x_mol, ei_mol, ea_mol, aggr_mol, cnt_mol, E_mol,
        x_prot, ei_prot, ea_prot, aggr_prot, cnt_prot, E_prot);

    gine_all<<<NM / 8 + NP / 8, 256>>>(
        x_mol, aggr_mol, cnt_mol, mol_w1, mol_b1, mol_w2, mol_b2,
        mp_wq, mp_bq, pm_wk, pm_bk, pm_wv, pm_bv, hmol, Qm, Km, Vm,
        x_prot, aggr_prot, cnt_prot, prot_w1, prot_b1, prot_w2, prot_b2,
        pm_wq, pm_bq, mp_wk, mp_bk, mp_wv, mp_bv, hprot, Qp, Kp, Vp);

    attn_all<<<2048, 256, 65536>>>(Qm, Kp, Vp, part_mol, Qp, Km, Vm, part_prot);

    combine_ln<<<NM, 64>>>(part_mol, SPLIT_M, NM, hmol, ln_mol_g, ln_mol_b, out);
    combine_ln<<<NP, 64>>>(part_prot, SPLIT_P, NP, hprot, ln_prot_g, ln_prot_b, out + NM * D);
}

// round 6
// speedup vs baseline: 3.4301x; 1.6928x over previous
#include <cuda_runtime.h>
#include <math_constants.h>

#define D 64
#define NM 2048
#define NP 8192
#define SPLIT_M 32
#define SPLIT_P 8
#define CHUNK 256

typedef unsigned long long u64;

// ---------------- f32x2 packed helpers ----------------
__device__ __forceinline__ u64 f2u2(float lo, float hi) {
    u64 r; asm("mov.b64 %0,{%1,%2};" : "=l"(r) : "f"(lo), "f"(hi)); return r;
}
__device__ __forceinline__ float2 u2f2(u64 v) {
    float2 r; asm("mov.b64 {%0,%1},%2;" : "=f"(r.x), "=f"(r.y) : "l"(v)); return r;
}
__device__ __forceinline__ u64 ffma2(u64 a, u64 b, u64 c) {
    u64 d; asm("fma.rn.f32x2 %0,%1,%2,%3;" : "=l"(d) : "l"(a), "l"(b), "l"(c)); return d;
}
__device__ __forceinline__ u64 fmul2(u64 a, u64 b) {
    u64 d; asm("mul.rn.f32x2 %0,%1,%2;" : "=l"(d) : "l"(a), "l"(b)); return d;
}
__device__ __forceinline__ u64 fadd2(u64 a, u64 b) {
    u64 d; asm("add.rn.f32x2 %0,%1,%2;" : "=l"(d) : "l"(a), "l"(b)); return d;
}

// bijective 16B-column permutation: identity on cols 0-7, rotate cols 8-15 by +2.
__device__ __forceinline__ int permc(int c) {
    return (c & 8) | ((c + ((c >> 2) & 2)) & 7);
}

__device__ __forceinline__ unsigned smem_u32(const void* p) {
    unsigned r;
    asm("{.reg .u64 t; cvta.to.shared.u64 t, %1; cvt.u32.u64 %0, t;}" : "=r"(r) : "l"(p));
    return r;
}

// ---------------- device scratch ----------------
__device__ float g_aggr_mol[NM * D];
__device__ float g_cnt_mol[NM];
__device__ float g_aggr_prot[NP * D];
__device__ float g_cnt_prot[NP];
__device__ float g_hmol[NM * D];
__device__ float g_hprot[NP * D];
__device__ float g_Qm[NM * D], g_Km[NM * D], g_Vm[NM * D];
__device__ float g_Qp[NP * D], g_Kp[NP * D], g_Vp[NP * D];
__device__ float g_part_mol[SPLIT_M * NM * 4 * 18];
__device__ float g_part_prot[SPLIT_P * NP * 4 * 18];

// ---------------- zero accumulators ----------------
__global__ void zero_all() {
    int i = blockIdx.x * blockDim.x + threadIdx.x;
    int stride = gridDim.x * blockDim.x;
    float4 z = make_float4(0.f, 0.f, 0.f, 0.f);
    for (int j = i; j < NM * D / 4; j += stride) ((float4*)g_aggr_mol)[j] = z;
    for (int j = i; j < NP * D / 4; j += stride) ((float4*)g_aggr_prot)[j] = z;
    for (int j = i; j < NM; j += stride) g_cnt_mol[j] = 0.f;
    for (int j = i; j < NP; j += stride) g_cnt_prot[j] = 0.f;
}

// ---------------- fused GINE edge scatter (both graphs, vector RED) ----------------
__global__ void edge_scatter_all(
    const float* __restrict__ xm, const int* __restrict__ eim, const float* __restrict__ eam,
    float* __restrict__ aggrm, float* __restrict__ cntm, int Em,
    const float* __restrict__ xp, const int* __restrict__ eip, const float* __restrict__ eap,
    float* __restrict__ aggrp, float* __restrict__ cntp, int Ep) {
    int idx = blockIdx.x * blockDim.x + threadIdx.x;
    const float* x;
    const int* ei;
    const float* ea;
    float* aggr;
    float* cnt;
    int E;
    if (idx < Em * 16) {
        x = xm; ei = eim; ea = eam; aggr = aggrm; cnt = cntm; E = Em;
    } else {
        idx -= Em * 16;
        if (idx >= Ep * 16) return;
        x = xp; ei = eip; ea = eap; aggr = aggrp; cnt = cntp; E = Ep;
    }
    int e = idx >> 4;
    int c = idx & 15;
    int src = ei[e];
    int dst = ei[E + e];
    float4 xv = __ldg((const float4*)(x + (size_t)src * D) + c);
    float4 ev = __ldg((const float4*)(ea + (size_t)e * D) + c);
    float mx = fmaxf(xv.x + ev.x, 0.f);
    float my = fmaxf(xv.y + ev.y, 0.f);
    float mz = fmaxf(xv.z + ev.z, 0.f);
    float mw = fmaxf(xv.w + ev.w, 0.f);
    float* a = aggr + (size_t)dst * D + c * 4;
    asm volatile("red.global.v4.f32.add [%0], {%1,%2,%3,%4};"
                 :: "l"(a), "f"(mx), "f"(my), "f"(mz), "f"(mw) : "memory");
    if (c == 0)
        asm volatile("red.global.add.f32 [%0], %1;" :: "l"(&cnt[dst]), "f"(1.0f) : "memory");
}

// ---------------- fused GINE node update + QKV projection (both node sets) ----------------
__global__ __launch_bounds__(256) void gine_all(
    const float* __restrict__ xm, const float* __restrict__ aggrm, const float* __restrict__ cntm,
    const float* __restrict__ mw1, const float* __restrict__ mb1,
    const float* __restrict__ mw2, const float* __restrict__ mb2,
    const float* __restrict__ mwq, const float* __restrict__ mbq,
    const float* __restrict__ mwk, const float* __restrict__ mbk,
    const float* __restrict__ mwv, const float* __restrict__ mbv,
    float* __restrict__ hm, float* __restrict__ Qm, float* __restrict__ Km, float* __restrict__ Vm,
    const float* __restrict__ xp, const float* __restrict__ aggrp, const float* __restrict__ cntp,
    const float* __restrict__ pw1, const float* __restrict__ pb1,
    const float* __restrict__ pw2, const float* __restrict__ pb2,
    const float* __restrict__ pwq, const float* __restrict__ pbq,
    const float* __restrict__ pwk, const float* __restrict__ pbk,
    const float* __restrict__ pwv, const float* __restrict__ pbv,
    float* __restrict__ hp, float* __restrict__ Qp, float* __restrict__ Kp, float* __restrict__ Vp) {
    const float *x, *aggr, *cnt, *w1, *b1, *w2, *b2, *wq, *bq, *wk, *bk, *wv, *bv;
    float *h_out, *Qo, *Ko, *Vo;
    int nb = blockIdx.x;
    if (nb < NM / 8) {
        x = xm; aggr = aggrm; cnt = cntm;
        w1 = mw1; b1 = mb1; w2 = mw2; b2 = mb2;
        wq = mwq; bq = mbq; wk = mwk; bk = mbk; wv = mwv; bv = mbv;
        h_out = hm; Qo = Qm; Ko = Km; Vo = Vm;
    } else {
        nb -= NM / 8;
        x = xp; aggr = aggrp; cnt = cntp;
        w1 = pw1; b1 = pb1; w2 = pw2; b2 = pb2;
        wq = pwq; bq = pbq; wk = pwk; bk = pbk; wv = pwv; bv = pbv;
        h_out = hp; Qo = Qp; Ko = Kp; Vo = Vp;
    }
    __shared__ float sv[8][D];
    int w = threadIdx.x >> 5;
    int lane = threadIdx.x & 31;
    int n = nb * 8 + w;
    int j = lane * 2;
    float inv = 1.f / fmaxf(cnt[n], 1.f);
    float2 xv = *(const float2*)(x + (size_t)n * D + j);
    float2 av = *(const float2*)(aggr + (size_t)n * D + j);
    sv[w][j] = fmaf(av.x, inv, xv.x);
    sv[w][j + 1] = fmaf(av.y, inv, xv.y);
    __syncwarp();

    float2 bb = __ldg((const float2*)(b1 + j));
    float a0 = bb.x, a1 = bb.y, a2 = 0.f, a3 = 0.f;
#pragma unroll
    for (int i = 0; i < D; i += 2) {
        float t0 = sv[w][i], t1 = sv[w][i + 1];
        float2 w0 = __ldg((const float2*)(w1 + i * D + j));
        float2 w1v = __ldg((const float2*)(w1 + (i + 1) * D + j));
        a0 = fmaf(t0, w0.x, a0);
        a1 = fmaf(t0, w0.y, a1);
        a2 = fmaf(t1, w1v.x, a2);
        a3 = fmaf(t1, w1v.y, a3);
    }
    float r0 = fmaxf(a0 + a2, 0.f), r1 = fmaxf(a1 + a3, 0.f);
    __syncwarp();
    sv[w][j] = r0;
    sv[w][j + 1] = r1;
    __syncwarp();

    bb = __ldg((const float2*)(b2 + j));
    a0 = bb.x; a1 = bb.y; a2 = 0.f; a3 = 0.f;
#pragma unroll
    for (int i = 0; i < D; i += 2) {
        float t0 = sv[w][i], t1 = sv[w][i + 1];
        float2 w0 = __ldg((const float2*)(w2 + i * D + j));
        float2 w1v = __ldg((const float2*)(w2 + (i + 1) * D + j));
        a0 = fmaf(t0, w0.x, a0);
        a1 = fmaf(t0, w0.y, a1);
        a2 = fmaf(t1, w1v.x, a2);
        a3 = fmaf(t1, w1v.y, a3);
    }
    float h0 = fmaxf(a0 + a2, 0.f), h1 = fmaxf(a1 + a3, 0.f);
    *(float2*)(h_out + (size_t)n * D + j) = make_float2(h0, h1);
    __syncwarp();
    sv[w][j] = h0;
    sv[w][j + 1] = h1;
    __syncwarp();

    float2 bq2 = __ldg((const float2*)(bq + j));
    float2 bk2 = __ldg((const float2*)(bk + j));
    float2 bv2 = __ldg((const float2*)(bv + j));
    float q0 = bq2.x, q1 = bq2.y, k0 = bk2.x, k1 = bk2.y, v0 = bv2.x, v1 = bv2.y;
#pragma unroll
    for (int i = 0; i < D; i++) {
        float t = sv[w][i];
        float2 wqv = __ldg((const float2*)(wq + i * D + j));
        float2 wkv = __ldg((const float2*)(wk + i * D + j));
        float2 wvv = __ldg((const float2*)(wv + i * D + j));
        q0 = fmaf(t, wqv.x, q0);
        q1 = fmaf(t, wqv.y, q1);
        k0 = fmaf(t, wkv.x, k0);
        k1 = fmaf(t, wkv.y, k1);
        v0 = fmaf(t, wvv.x, v0);
        v1 = fmaf(t, wvv.y, v1);
    }
    *(float2*)(Qo + (size_t)n * D + j) = make_float2(q0, q1);
    *(float2*)(Ko + (size_t)n * D + j) = make_float2(k0, k1);
    *(float2*)(Vo + (size_t)n * D + j) = make_float2(v0, v1);
}

// ---------------- unified split-K flash attention, 2 queries/thread ----------------
// 128 threads/block; thread t owns queries (qt*64 + t>>2) and (+32), head t&3.
// K/V slices loaded once per key, reused for both queries -> halves smem traffic.
__global__ __launch_bounds__(128, 3) void attn_all(
    const float* __restrict__ Qm, const float* __restrict__ Kp, const float* __restrict__ Vp,
    float* __restrict__ partM,
    const float* __restrict__ Qp, const float* __restrict__ Km, const float* __restrict__ Vm,
    float* __restrict__ partP) {
    extern __shared__ ulonglong2 smem[];
    ulonglong2* sK = smem;          // [2][1024]
    ulonglong2* sV = smem + 2048;   // [2][1024]
    unsigned sK_u32 = smem_u32(sK);
    unsigned sV_u32 = smem_u32(sV);

    int b = blockIdx.x;
    const float *Q, *K, *V;
    float* part;
    int Nq, qt, sp;
    if (b < 1024) {
        Q = Qm; K = Kp; V = Vp; part = partM; Nq = NM;
        qt = b >> 5; sp = b & 31;
    } else {
        int b2 = b - 1024;
        Q = Qp; K = Km; V = Vm; part = partP; Nq = NP;
        qt = b2 >> 3; sp = b2 & 7;
    }
    int t = threadIdx.x;
    int h = t & 3;
    int qa = qt * 64 + (t >> 2);
    int qb = qa + 32;
    int k0 = sp * CHUNK;

    int pc[4];
#pragma unroll
    for (int i = 0; i < 4; i++) pc[i] = permc(h * 4 + i);

    // per-thread smem dst offsets (permuted) for the 8 chunks it copies each tile
    unsigned dsts[8];
#pragma unroll
    for (int r = 0; r < 8; r++) {
        int idx = t + r * 128;
        int row = idx >> 4;
        int col = idx & 15;
        dsts[r] = (unsigned)((row * 16 + permc(col)) * 16);
    }

    u64 qpA[8], qpB[8];
    {
        const float4* Qv = (const float4*)(Q + (size_t)qa * D + h * 16);
#pragma unroll
        for (int r = 0; r < 4; r++) {
            float4 v = Qv[r];
            qpA[r * 2 + 0] = f2u2(v.x * 0.25f, v.y * 0.25f);
            qpA[r * 2 + 1] = f2u2(v.z * 0.25f, v.w * 0.25f);
        }
        const float4* Qw = (const float4*)(Q + (size_t)qb * D + h * 16);
#pragma unroll
        for (int r = 0; r < 4; r++) {
            float4 v = Qw[r];
            qpB[r * 2 + 0] = f2u2(v.x * 0.25f, v.y * 0.25f);
            qpB[r * 2 + 1] = f2u2(v.z * 0.25f, v.w * 0.25f);
        }
    }

    float m0 = -CUDART_INF_F, m1 = -CUDART_INF_F;
    float l0 = 0.f, l1 = 0.f;
    u64 accA[8], accB[8];
#pragma unroll
    for (int i = 0; i < 8; i++) { accA[i] = 0ull; accB[i] = 0ull; }

    // prefetch tile 0
    {
        const char* Kg = (const char*)(K + (size_t)k0 * D);
        const char* Vg = (const char*)(V + (size_t)k0 * D);
#pragma unroll
        for (int r = 0; r < 8; r++) {
            int idx = t + r * 128;
            asm volatile("cp.async.cg.shared.global [%0], [%1], 16;"
                         :: "r"(sK_u32 + dsts[r]), "l"(Kg + idx * 16) : "memory");
            asm volatile("cp.async.cg.shared.global [%0], [%1], 16;"
                         :: "r"(sV_u32 + dsts[r]), "l"(Vg + idx * 16) : "memory");
        }
        asm volatile("cp.async.commit_group;" ::: "memory");
    }

#pragma unroll
    for (int tile = 0; tile < 4; tile++) {
        int buf = tile & 1;
        if (tile < 3) {
            int nbuf = (tile + 1) & 1;
            const char* Kg = (const char*)(K + (size_t)(k0 + (tile + 1) * 64) * D);
            const char* Vg = (const char*)(V + (size_t)(k0 + (tile + 1) * 64) * D);
            unsigned kb = sK_u32 + nbuf * 16384;
            unsigned vb = sV_u32 + nbuf * 16384;
#pragma unroll
            for (int r = 0; r < 8; r++) {
                int idx = t + r * 128;
                asm volatile("cp.async.cg.shared.global [%0], [%1], 16;"
                             :: "r"(kb + dsts[r]), "l"(Kg + idx * 16) : "memory");
                asm volatile("cp.async.cg.shared.global [%0], [%1], 16;"
                             :: "r"(vb + dsts[r]), "l"(Vg + idx * 16) : "memory");
            }
            asm volatile("cp.async.commit_group;" ::: "memory");
            asm volatile("cp.async.wait_group 1;" ::: "memory");
        } else {
            asm volatile("cp.async.wait_group 0;" ::: "memory");
        }
        __syncthreads();

        const ulonglong2* kbase = sK + buf * 1024;
        const ulonglong2* vbase = sV + buf * 1024;
        for (int sub = 0; sub < 8; sub++) {
            float s0[8], s1[8];
#pragma unroll
            for (int kk = 0; kk < 8; kk++) {
                int key = sub * 8 + kk;
                ulonglong2 ka = kbase[key * 16 + pc[0]];
                ulonglong2 kb2 = kbase[key * 16 + pc[1]];
                ulonglong2 kc = kbase[key * 16 + pc[2]];
                ulonglong2 kd = kbase[key * 16 + pc[3]];
                u64 sa = fmul2(qpA[0], ka.x);
                u64 sb = fmul2(qpA[1], ka.y);
                sa = ffma2(qpA[2], kb2.x, sa);
                sb = ffma2(qpA[3], kb2.y, sb);
                sa = ffma2(qpA[4], kc.x, sa);
                sb = ffma2(qpA[5], kc.y, sb);
                sa = ffma2(qpA[6], kd.x, sa);
                sb = ffma2(qpA[7], kd.y, sb);
                float2 f = u2f2(fadd2(sa, sb));
                s0[kk] = f.x + f.y;
                u64 ta = fmul2(qpB[0], ka.x);
                u64 tb = fmul2(qpB[1], ka.y);
                ta = ffma2(qpB[2], kb2.x, ta);
                tb = ffma2(qpB[3], kb2.y, tb);
                ta = ffma2(qpB[4], kc.x, ta);
                tb = ffma2(qpB[5], kc.y, tb);
                ta = ffma2(qpB[6], kd.x, ta);
                tb = ffma2(qpB[7], kd.y, tb);
                float2 g = u2f2(fadd2(ta, tb));
                s1[kk] = g.x + g.y;
            }
            // per-query sub-tile max + rescale
            {
                float t01 = fmaxf(s0[0], s0[1]), t23 = fmaxf(s0[2], s0[3]);
                float t45 = fmaxf(s0[4], s0[5]), t67 = fmaxf(s0[6], s0[7]);
                float tm = fmaxf(fmaxf(t01, t23), fmaxf(t45, t67));
                float mn = fmaxf(m0, tm);
                float corr = __expf(m0 - mn);
                m0 = mn;
                l0 *= corr;
                u64 cc = f2u2(corr, corr);
#pragma unroll
                for (int i = 0; i < 8; i++) accA[i] = fmul2(accA[i], cc);
            }
            {
                float t01 = fmaxf(s1[0], s1[1]), t23 = fmaxf(s1[2], s1[3]);
                float t45 = fmaxf(s1[4], s1[5]), t67 = fmaxf(s1[6], s1[7]);
                float tm = fmaxf(fmaxf(t01, t23), fmaxf(t45, t67));
                float mn = fmaxf(m1, tm);
                float corr = __expf(m1 - mn);
                m1 = mn;
                l1 *= corr;
                u64 cc = f2u2(corr, corr);
#pragma unroll
                for (int i = 0; i < 8; i++) accB[i] = fmul2(accB[i], cc);
            }

#pragma unroll
            for (int kk = 0; kk < 8; kk++) {
                int key = sub * 8 + kk;
                float p0 = __expf(s0[kk] - m0);
                float p1 = __expf(s1[kk] - m1);
                l0 += p0;
                l1 += p1;
                u64 pp0 = f2u2(p0, p0);
                u64 pp1 = f2u2(p1, p1);
                ulonglong2 va = vbase[key * 16 + pc[0]];
                ulonglong2 vb2 = vbase[key * 16 + pc[1]];
                ulonglong2 vc = vbase[key * 16 + pc[2]];
                ulonglong2 vd = vbase[key * 16 + pc[3]];
                accA[0] = ffma2(pp0, va.x, accA[0]);
                accB[0] = ffma2(pp1, va.x, accB[0]);
                accA[1] = ffma2(pp0, va.y, accA[1]);
                accB[1] = ffma2(pp1, va.y, accB[1]);
                accA[2] = ffma2(pp0, vb2.x, accA[2]);
                accB[2] = ffma2(pp1, vb2.x, accB[2]);
                accA[3] = ffma2(pp0, vb2.y, accA[3]);
                accB[3] = ffma2(pp1, vb2.y, accB[3]);
                accA[4] = ffma2(pp0, vc.x, accA[4]);
                accB[4] = ffma2(pp1, vc.x, accB[4]);
                accA[5] = ffma2(pp0, vc.y, accA[5]);
                accB[5] = ffma2(pp1, vc.y, accB[5]);
                accA[6] = ffma2(pp0, vd.x, accA[6]);
                accB[6] = ffma2(pp1, vd.x, accB[6]);
                accA[7] = ffma2(pp0, vd.y, accA[7]);
                accB[7] = ffma2(pp1, vd.y, accB[7]);
            }
        }
        __syncthreads();
    }
    {
        int row = sp * (Nq * 4) + qa * 4 + h;
        float* pw = part + (size_t)row * 18;
        pw[0] = m0;
        pw[1] = l0;
#pragma unroll
        for (int i = 0; i < 8; i++) {
            float2 f = u2f2(accA[i]);
            pw[2 + i * 2] = f.x;
            pw[3 + i * 2] = f.y;
        }
    }
    {
        int row = sp * (Nq * 4) + qb * 4 + h;
        float* pw = part + (size_t)row * 18;
        pw[0] = m1;
        pw[1] = l1;
#pragma unroll
        for (int i = 0; i < 8; i++) {
            float2 f = u2f2(accB[i]);
            pw[2 + i * 2] = f.x;
            pw[3 + i * 2] = f.y;
        }
    }
}

// ---------------- combine partials + residual + layernorm ----------------
__global__ void combine_ln(const float* __restrict__ part, int S, int Nq,
                           const float* __restrict__ hres, const float* __restrict__ g,
                           const float* __restrict__ b, float* __restrict__ out) {
    __shared__ float red[D];
    __shared__ float red2[D];
    int q = blockIdx.x;
    int d = threadIdx.x;
    int h = d >> 4;
    int i = d & 15;
    int rowbase = q * 4 + h;

    float M = -CUDART_INF_F;
    for (int s = 0; s < S; s++) M = fmaxf(M, part[(size_t)(s * Nq * 4 + rowbase) * 18]);
    float num = 0.f, den = 0.f;
    for (int s = 0; s < S; s++) {
        const float* pp = part + (size_t)(s * Nq * 4 + rowbase) * 18;
        float e = __expf(pp[0] - M);
        den += e * pp[1];
        num += e * pp[2 + i];
    }
    float val = num / den + hres[(size_t)q * D + d];

    red[d] = val;
    red2[d] = val * val;
    __syncthreads();
    for (int off = 32; off >= 1; off >>= 1) {
        if (d < off) {
            red[d] += red[d + off];
            red2[d] += red2[d + off];
        }
        __syncthreads();
    }
    float mu = red[0] * (1.f / 64.f);
    float var = red2[0] * (1.f / 64.f) - mu * mu;
    float r = rsqrtf(var + 1e-5f);
    out[(size_t)q * D + d] = (val - mu) * r * g[d] + b[d];
}

// ---------------- launch ----------------
extern "C" void kernel_launch(void* const* d_in, const int* in_sizes, int n_in,
                              void* d_out, int out_size) {
    const float* x_mol = (const float*)d_in[0];
    const int* ei_mol = (const int*)d_in[1];
    const float* ea_mol = (const float*)d_in[2];
    const float* x_prot = (const float*)d_in[3];
    const int* ei_prot = (const int*)d_in[4];
    const float* ea_prot = (const float*)d_in[5];
    const float* mol_w1 = (const float*)d_in[6];
    const float* mol_b1 = (const float*)d_in[7];
    const float* mol_w2 = (const float*)d_in[8];
    const float* mol_b2 = (const float*)d_in[9];
    const float* prot_w1 = (const float*)d_in[10];
    const float* prot_b1 = (const float*)d_in[11];
    const float* prot_w2 = (const float*)d_in[12];
    const float* prot_b2 = (const float*)d_in[13];
    const float* mp_wq = (const float*)d_in[14];
    const float* mp_bq = (const float*)d_in[15];
    const float* mp_wk = (const float*)d_in[16];
    const float* mp_bk = (const float*)d_in[17];
    const float* mp_wv = (const float*)d_in[18];
    const float* mp_bv = (const float*)d_in[19];
    const float* pm_wq = (const float*)d_in[20];
    const float* pm_bq = (const float*)d_in[21];
    const float* pm_wk = (const float*)d_in[22];
    const float* pm_bk = (const float*)d_in[23];
    const float* pm_wv = (const float*)d_in[24];
    const float* pm_bv = (const float*)d_in[25];
    const float* ln_mol_g = (const float*)d_in[26];
    const float* ln_mol_b = (const float*)d_in[27];
    const float* ln_prot_g = (const float*)d_in[28];
    const float* ln_prot_b = (const float*)d_in[29];

    int E_mol = in_sizes[1] / 2;
    int E_prot = in_sizes[4] / 2;
    float* out = (float*)d_out;

    float *aggr_mol, *cnt_mol, *aggr_prot, *cnt_prot;
    float *hmol, *hprot, *Qm, *Km, *Vm, *Qp, *Kp, *Vp, *part_mol, *part_prot;
    cudaGetSymbolAddress((void**)&aggr_mol, g_aggr_mol);
    cudaGetSymbolAddress((void**)&cnt_mol, g_cnt_mol);
    cudaGetSymbolAddress((void**)&aggr_prot, g_aggr_prot);
    cudaGetSymbolAddress((void**)&cnt_prot, g_cnt_prot);
    cudaGetSymbolAddress((void**)&hmol, g_hmol);
    cudaGetSymbolAddress((void**)&hprot, g_hprot);
    cudaGetSymbolAddress((void**)&Qm, g_Qm);
    cudaGetSymbolAddress((void**)&Km, g_Km);
    cudaGetSymbolAddress((void**)&Vm, g_Vm);
    cudaGetSymbolAddress((void**)&Qp, g_Qp);
    cudaGetSymbolAddress((void**)&Kp, g_Kp);
    cudaGetSymbolAddress((void**)&Vp, g_Vp);
    cudaGetSymbolAddress((void**)&part_mol, g_part_mol);
    cudaGetSymbolAddress((void**)&part_prot, g_part_prot);

    static int smem_set = 0;
    if (!smem_set) {
        cudaFuncSetAttribute(attn_all, cudaFuncAttributeMaxDynamicSharedMemorySize, 65536);
        smem_set = 1;
    }

    zero_all<<<256, 256>>>();

    int total_scatter = (E_mol + E_prot) * 16;
    edge_scatter_all<<<(total_scatter + 255) / 256, 256>>>(
        x_mol, ei_mol, ea_mol, aggr_mol, cnt_mol, E_mol,
        x_prot, ei_prot, ea_prot, aggr_prot, cnt_prot, E_prot);

    gine_all<<<NM / 8 + NP / 8, 256>>>(
        x_mol, aggr_mol, cnt_mol, mol_w1, mol_b1, mol_w2, mol_b2,
        mp_wq, mp_bq, pm_wk, pm_bk, pm_wv, pm_bv, hmol, Qm, Km, Vm,
        x_prot, aggr_prot, cnt_prot, prot_w1, prot_b1, prot_w2, prot_b2,
        pm_wq, pm_bq, mp_wk, mp_bk, mp_wv, mp_bv, hprot, Qp, Kp, Vp);

    attn_all<<<2048, 128, 65536>>>(Qm, Kp, Vp, part_mol, Qp, Km, Vm, part_prot);

    combine_ln<<<NM, 64>>>(part_mol, SPLIT_M, NM, hmol, ln_mol_g, ln_mol_b, out);
    combine_ln<<<NP, 64>>>(part_prot, SPLIT_P, NP, hprot, ln_prot_g, ln_prot_b, out + NM * D);
}

// round 7
// speedup vs baseline: 3.7589x; 1.0959x over previous
#include <cuda_runtime.h>
#include <math_constants.h>

#define D 64
#define NM 2048
#define NP 8192
#define SPLIT_M 32
#define SPLIT_P 8
#define CHUNK 256

typedef unsigned long long u64;

// ---------------- f32x2 packed helpers ----------------
__device__ __forceinline__ u64 f2u2(float lo, float hi) {
    u64 r; asm("mov.b64 %0,{%1,%2};" : "=l"(r) : "f"(lo), "f"(hi)); return r;
}
__device__ __forceinline__ float2 u2f2(u64 v) {
    float2 r; asm("mov.b64 {%0,%1},%2;" : "=f"(r.x), "=f"(r.y) : "l"(v)); return r;
}
__device__ __forceinline__ u64 ffma2(u64 a, u64 b, u64 c) {
    u64 d; asm("fma.rn.f32x2 %0,%1,%2,%3;" : "=l"(d) : "l"(a), "l"(b), "l"(c)); return d;
}
__device__ __forceinline__ u64 fmul2(u64 a, u64 b) {
    u64 d; asm("mul.rn.f32x2 %0,%1,%2;" : "=l"(d) : "l"(a), "l"(b)); return d;
}
__device__ __forceinline__ u64 fadd2(u64 a, u64 b) {
    u64 d; asm("add.rn.f32x2 %0,%1,%2;" : "=l"(d) : "l"(a), "l"(b)); return d;
}

// bijective 16B-column permutation: identity on cols 0-7, rotate cols 8-15 by +2.
__device__ __forceinline__ int permc(int c) {
    return (c & 8) | ((c + ((c >> 2) & 2)) & 7);
}

__device__ __forceinline__ unsigned smem_u32(const void* p) {
    unsigned r;
    asm("{.reg .u64 t; cvta.to.shared.u64 t, %1; cvt.u32.u64 %0, t;}" : "=r"(r) : "l"(p));
    return r;
}

// ---------------- device scratch ----------------
__device__ float g_aggr_mol[NM * D];
__device__ float g_cnt_mol[NM];
__device__ float g_aggr_prot[NP * D];
__device__ float g_cnt_prot[NP];
__device__ float g_hmol[NM * D];
__device__ float g_hprot[NP * D];
__device__ float g_Qm[NM * D], g_Km[NM * D], g_Vm[NM * D];
__device__ float g_Qp[NP * D], g_Kp[NP * D], g_Vp[NP * D];
__device__ float g_part_mol[SPLIT_M * NM * 4 * 18];
__device__ float g_part_prot[SPLIT_P * NP * 4 * 18];

// ---------------- zero accumulators ----------------
__global__ void zero_all() {
    int i = blockIdx.x * blockDim.x + threadIdx.x;
    int stride = gridDim.x * blockDim.x;
    float4 z = make_float4(0.f, 0.f, 0.f, 0.f);
    for (int j = i; j < NM * D / 4; j += stride) ((float4*)g_aggr_mol)[j] = z;
    for (int j = i; j < NP * D / 4; j += stride) ((float4*)g_aggr_prot)[j] = z;
    for (int j = i; j < NM; j += stride) g_cnt_mol[j] = 0.f;
    for (int j = i; j < NP; j += stride) g_cnt_prot[j] = 0.f;
}

// ---------------- fused GINE edge scatter (both graphs, vector RED) ----------------
__global__ void edge_scatter_all(
    const float* __restrict__ xm, const int* __restrict__ eim, const float* __restrict__ eam,
    float* __restrict__ aggrm, float* __restrict__ cntm, int Em,
    const float* __restrict__ xp, const int* __restrict__ eip, const float* __restrict__ eap,
    float* __restrict__ aggrp, float* __restrict__ cntp, int Ep) {
    int idx = blockIdx.x * blockDim.x + threadIdx.x;
    const float* x;
    const int* ei;
    const float* ea;
    float* aggr;
    float* cnt;
    int E;
    if (idx < Em * 16) {
        x = xm; ei = eim; ea = eam; aggr = aggrm; cnt = cntm; E = Em;
    } else {
        idx -= Em * 16;
        if (idx >= Ep * 16) return;
        x = xp; ei = eip; ea = eap; aggr = aggrp; cnt = cntp; E = Ep;
    }
    int e = idx >> 4;
    int c = idx & 15;
    int src = ei[e];
    int dst = ei[E + e];
    float4 xv = __ldg((const float4*)(x + (size_t)src * D) + c);
    float4 ev = __ldg((const float4*)(ea + (size_t)e * D) + c);
    float mx = fmaxf(xv.x + ev.x, 0.f);
    float my = fmaxf(xv.y + ev.y, 0.f);
    float mz = fmaxf(xv.z + ev.z, 0.f);
    float mw = fmaxf(xv.w + ev.w, 0.f);
    float* a = aggr + (size_t)dst * D + c * 4;
    asm volatile("red.global.v4.f32.add [%0], {%1,%2,%3,%4};"
                 :: "l"(a), "f"(mx), "f"(my), "f"(mz), "f"(mw) : "memory");
    if (c == 0)
        asm volatile("red.global.add.f32 [%0], %1;" :: "l"(&cnt[dst]), "f"(1.0f) : "memory");
}

// ---------------- fused GINE node update + QKV projection (both node sets) ----------------
__global__ __launch_bounds__(256) void gine_all(
    const float* __restrict__ xm, const float* __restrict__ aggrm, const float* __restrict__ cntm,
    const float* __restrict__ mw1, const float* __restrict__ mb1,
    const float* __restrict__ mw2, const float* __restrict__ mb2,
    const float* __restrict__ mwq, const float* __restrict__ mbq,
    const float* __restrict__ mwk, const float* __restrict__ mbk,
    const float* __restrict__ mwv, const float* __restrict__ mbv,
    float* __restrict__ hm, float* __restrict__ Qm, float* __restrict__ Km, float* __restrict__ Vm,
    const float* __restrict__ xp, const float* __restrict__ aggrp, const float* __restrict__ cntp,
    const float* __restrict__ pw1, const float* __restrict__ pb1,
    const float* __restrict__ pw2, const float* __restrict__ pb2,
    const float* __restrict__ pwq, const float* __restrict__ pbq,
    const float* __restrict__ pwk, const float* __restrict__ pbk,
    const float* __restrict__ pwv, const float* __restrict__ pbv,
    float* __restrict__ hp, float* __restrict__ Qp, float* __restrict__ Kp, float* __restrict__ Vp) {
    const float *x, *aggr, *cnt, *w1, *b1, *w2, *b2, *wq, *bq, *wk, *bk, *wv, *bv;
    float *h_out, *Qo, *Ko, *Vo;
    int nb = blockIdx.x;
    if (nb < NM / 8) {
        x = xm; aggr = aggrm; cnt = cntm;
        w1 = mw1; b1 = mb1; w2 = mw2; b2 = mb2;
        wq = mwq; bq = mbq; wk = mwk; bk = mbk; wv = mwv; bv = mbv;
        h_out = hm; Qo = Qm; Ko = Km; Vo = Vm;
    } else {
        nb -= NM / 8;
        x = xp; aggr = aggrp; cnt = cntp;
        w1 = pw1; b1 = pb1; w2 = pw2; b2 = pb2;
        wq = pwq; bq = pbq; wk = pwk; bk = pbk; wv = pwv; bv = pbv;
        h_out = hp; Qo = Qp; Ko = Kp; Vo = Vp;
    }
    __shared__ float sv[8][D];
    int w = threadIdx.x >> 5;
    int lane = threadIdx.x & 31;
    int n = nb * 8 + w;
    int j = lane * 2;
    float inv = 1.f / fmaxf(cnt[n], 1.f);
    float2 xv = *(const float2*)(x + (size_t)n * D + j);
    float2 av = *(const float2*)(aggr + (size_t)n * D + j);
    sv[w][j] = fmaf(av.x, inv, xv.x);
    sv[w][j + 1] = fmaf(av.y, inv, xv.y);
    __syncwarp();

    float2 bb = __ldg((const float2*)(b1 + j));
    float a0 = bb.x, a1 = bb.y, a2 = 0.f, a3 = 0.f;
#pragma unroll
    for (int i = 0; i < D; i += 2) {
        float t0 = sv[w][i], t1 = sv[w][i + 1];
        float2 w0 = __ldg((const float2*)(w1 + i * D + j));
        float2 w1v = __ldg((const float2*)(w1 + (i + 1) * D + j));
        a0 = fmaf(t0, w0.x, a0);
        a1 = fmaf(t0, w0.y, a1);
        a2 = fmaf(t1, w1v.x, a2);
        a3 = fmaf(t1, w1v.y, a3);
    }
    float r0 = fmaxf(a0 + a2, 0.f), r1 = fmaxf(a1 + a3, 0.f);
    __syncwarp();
    sv[w][j] = r0;
    sv[w][j + 1] = r1;
    __syncwarp();

    bb = __ldg((const float2*)(b2 + j));
    a0 = bb.x; a1 = bb.y; a2 = 0.f; a3 = 0.f;
#pragma unroll
    for (int i = 0; i < D; i += 2) {
        float t0 = sv[w][i], t1 = sv[w][i + 1];
        float2 w0 = __ldg((const float2*)(w2 + i * D + j));
        float2 w1v = __ldg((const float2*)(w2 + (i + 1) * D + j));
        a0 = fmaf(t0, w0.x, a0);
        a1 = fmaf(t0, w0.y, a1);
        a2 = fmaf(t1, w1v.x, a2);
        a3 = fmaf(t1, w1v.y, a3);
    }
    float h0 = fmaxf(a0 + a2, 0.f), h1 = fmaxf(a1 + a3, 0.f);
    *(float2*)(h_out + (size_t)n * D + j) = make_float2(h0, h1);
    __syncwarp();
    sv[w][j] = h0;
    sv[w][j + 1] = h1;
    __syncwarp();

    float2 bq2 = __ldg((const float2*)(bq + j));
    float2 bk2 = __ldg((const float2*)(bk + j));
    float2 bv2 = __ldg((const float2*)(bv + j));
    float q0 = bq2.x, q1 = bq2.y, k0 = bk2.x, k1 = bk2.y, v0 = bv2.x, v1 = bv2.y;
#pragma unroll
    for (int i = 0; i < D; i++) {
        float t = sv[w][i];
        float2 wqv = __ldg((const float2*)(wq + i * D + j));
        float2 wkv = __ldg((const float2*)(wk + i * D + j));
        float2 wvv = __ldg((const float2*)(wv + i * D + j));
        q0 = fmaf(t, wqv.x, q0);
        q1 = fmaf(t, wqv.y, q1);
        k0 = fmaf(t, wkv.x, k0);
        k1 = fmaf(t, wkv.y, k1);
        v0 = fmaf(t, wvv.x, v0);
        v1 = fmaf(t, wvv.y, v1);
    }
    *(float2*)(Qo + (size_t)n * D + j) = make_float2(q0, q1);
    *(float2*)(Ko + (size_t)n * D + j) = make_float2(k0, k1);
    *(float2*)(Vo + (size_t)n * D + j) = make_float2(v0, v1);
}

// ---------------- unified split-K flash attention, 4 queries/thread ----------------
// 128 threads/block, 128-query x 256-key tiles. Thread t: head t&3, queries
// qt*128 + (t>>2) + {0,32,64,96}. K/V slices loaded once per key, reused 4x.
__global__ __launch_bounds__(128) void attn_all(
    const float* __restrict__ Qm, const float* __restrict__ Kp, const float* __restrict__ Vp,
    float* __restrict__ partM,
    const float* __restrict__ Qp, const float* __restrict__ Km, const float* __restrict__ Vm,
    float* __restrict__ partP) {
    extern __shared__ ulonglong2 smem[];
    ulonglong2* sK = smem;          // [2][1024]
    ulonglong2* sV = smem + 2048;   // [2][1024]
    unsigned sK_u32 = smem_u32(sK);
    unsigned sV_u32 = smem_u32(sV);

    int b = blockIdx.x;
    const float *Q, *K, *V;
    float* part;
    int Nq, qt, sp;
    if (b < 512) {
        Q = Qm; K = Kp; V = Vp; part = partM; Nq = NM;
        qt = b >> 5; sp = b & 31;           // 16 q-tiles x 32 splits
    } else {
        int b2 = b - 512;
        Q = Qp; K = Km; V = Vm; part = partP; Nq = NP;
        qt = b2 >> 3; sp = b2 & 7;          // 64 q-tiles x 8 splits
    }
    int t = threadIdx.x;
    int h = t & 3;
    int qbase = qt * 128 + (t >> 2);
    int k0 = sp * CHUNK;

    int pc[4];
#pragma unroll
    for (int i = 0; i < 4; i++) pc[i] = permc(h * 4 + i);

    unsigned dsts[8];
#pragma unroll
    for (int r = 0; r < 8; r++) {
        int idx = t + r * 128;
        int row = idx >> 4;
        int col = idx & 15;
        dsts[r] = (unsigned)((row * 16 + permc(col)) * 16);
    }

    u64 qp[4][8];
#pragma unroll
    for (int jq = 0; jq < 4; jq++) {
        const float4* Qv = (const float4*)(Q + (size_t)(qbase + jq * 32) * D + h * 16);
#pragma unroll
        for (int r = 0; r < 4; r++) {
            float4 v = Qv[r];
            qp[jq][r * 2 + 0] = f2u2(v.x * 0.25f, v.y * 0.25f);
            qp[jq][r * 2 + 1] = f2u2(v.z * 0.25f, v.w * 0.25f);
        }
    }

    float m[4], l[4];
    u64 acc[4][8];
#pragma unroll
    for (int jq = 0; jq < 4; jq++) {
        m[jq] = -CUDART_INF_F;
        l[jq] = 0.f;
#pragma unroll
        for (int i = 0; i < 8; i++) acc[jq][i] = 0ull;
    }

    // prefetch tile 0
    {
        const char* Kg = (const char*)(K + (size_t)k0 * D);
        const char* Vg = (const char*)(V + (size_t)k0 * D);
#pragma unroll
        for (int r = 0; r < 8; r++) {
            int idx = t + r * 128;
            asm volatile("cp.async.cg.shared.global [%0], [%1], 16;"
                         :: "r"(sK_u32 + dsts[r]), "l"(Kg + idx * 16) : "memory");
            asm volatile("cp.async.cg.shared.global [%0], [%1], 16;"
                         :: "r"(sV_u32 + dsts[r]), "l"(Vg + idx * 16) : "memory");
        }
        asm volatile("cp.async.commit_group;" ::: "memory");
    }

#pragma unroll
    for (int tile = 0; tile < 4; tile++) {
        int buf = tile & 1;
        if (tile < 3) {
            int nbuf = (tile + 1) & 1;
            const char* Kg = (const char*)(K + (size_t)(k0 + (tile + 1) * 64) * D);
            const char* Vg = (const char*)(V + (size_t)(k0 + (tile + 1) * 64) * D);
            unsigned kb = sK_u32 + nbuf * 16384;
            unsigned vb = sV_u32 + nbuf * 16384;
#pragma unroll
            for (int r = 0; r < 8; r++) {
                int idx = t + r * 128;
                asm volatile("cp.async.cg.shared.global [%0], [%1], 16;"
                             :: "r"(kb + dsts[r]), "l"(Kg + idx * 16) : "memory");
                asm volatile("cp.async.cg.shared.global [%0], [%1], 16;"
                             :: "r"(vb + dsts[r]), "l"(Vg + idx * 16) : "memory");
            }
            asm volatile("cp.async.commit_group;" ::: "memory");
            asm volatile("cp.async.wait_group 1;" ::: "memory");
        } else {
            asm volatile("cp.async.wait_group 0;" ::: "memory");
        }
        __syncthreads();

        const ulonglong2* kbase = sK + buf * 1024;
        const ulonglong2* vbase = sV + buf * 1024;
        for (int sub = 0; sub < 8; sub++) {
            float s[4][8];
#pragma unroll
            for (int kk = 0; kk < 8; kk++) {
                int key = sub * 8 + kk;
                ulonglong2 ka = kbase[key * 16 + pc[0]];
                ulonglong2 kb2 = kbase[key * 16 + pc[1]];
                ulonglong2 kc = kbase[key * 16 + pc[2]];
                ulonglong2 kd = kbase[key * 16 + pc[3]];
#pragma unroll
                for (int jq = 0; jq < 4; jq++) {
                    u64 sa = fmul2(qp[jq][0], ka.x);
                    u64 sb = fmul2(qp[jq][1], ka.y);
                    sa = ffma2(qp[jq][2], kb2.x, sa);
                    sb = ffma2(qp[jq][3], kb2.y, sb);
                    sa = ffma2(qp[jq][4], kc.x, sa);
                    sb = ffma2(qp[jq][5], kc.y, sb);
                    sa = ffma2(qp[jq][6], kd.x, sa);
                    sb = ffma2(qp[jq][7], kd.y, sb);
                    float2 f = u2f2(fadd2(sa, sb));
                    s[jq][kk] = f.x + f.y;
                }
            }
#pragma unroll
            for (int jq = 0; jq < 4; jq++) {
                float t01 = fmaxf(s[jq][0], s[jq][1]), t23 = fmaxf(s[jq][2], s[jq][3]);
                float t45 = fmaxf(s[jq][4], s[jq][5]), t67 = fmaxf(s[jq][6], s[jq][7]);
                float tm = fmaxf(fmaxf(t01, t23), fmaxf(t45, t67));
                float mn = fmaxf(m[jq], tm);
                float corr = __expf(m[jq] - mn);  // exp(-inf)=0 on first tile
                m[jq] = mn;
                l[jq] *= corr;
                u64 cc = f2u2(corr, corr);
#pragma unroll
                for (int i = 0; i < 8; i++) acc[jq][i] = fmul2(acc[jq][i], cc);
            }

#pragma unroll
            for (int kk = 0; kk < 8; kk++) {
                int key = sub * 8 + kk;
                u64 pp[4];
#pragma unroll
                for (int jq = 0; jq < 4; jq++) {
                    float p = __expf(s[jq][kk] - m[jq]);
                    l[jq] += p;
                    pp[jq] = f2u2(p, p);
                }
                ulonglong2 va = vbase[key * 16 + pc[0]];
                ulonglong2 vb2 = vbase[key * 16 + pc[1]];
                ulonglong2 vc = vbase[key * 16 + pc[2]];
                ulonglong2 vd = vbase[key * 16 + pc[3]];
#pragma unroll
                for (int jq = 0; jq < 4; jq++) {
                    acc[jq][0] = ffma2(pp[jq], va.x, acc[jq][0]);
                    acc[jq][1] = ffma2(pp[jq], va.y, acc[jq][1]);
                    acc[jq][2] = ffma2(pp[jq], vb2.x, acc[jq][2]);
                    acc[jq][3] = ffma2(pp[jq], vb2.y, acc[jq][3]);
                    acc[jq][4] = ffma2(pp[jq], vc.x, acc[jq][4]);
                    acc[jq][5] = ffma2(pp[jq], vc.y, acc[jq][5]);
                    acc[jq][6] = ffma2(pp[jq], vd.x, acc[jq][6]);
                    acc[jq][7] = ffma2(pp[jq], vd.y, acc[jq][7]);
                }
            }
        }
        __syncthreads();
    }
#pragma unroll
    for (int jq = 0; jq < 4; jq++) {
        int row = sp * (Nq * 4) + (qbase + jq * 32) * 4 + h;
        float* pw = part + (size_t)row * 18;
        pw[0] = m[jq];
        pw[1] = l[jq];
#pragma unroll
        for (int i = 0; i < 8; i++) {
            float2 f = u2f2(acc[jq][i]);
            pw[2 + i * 2] = f.x;
            pw[3 + i * 2] = f.y;
        }
    }
}

// ---------------- combine partials + residual + layernorm ----------------
__global__ void combine_ln(const float* __restrict__ part, int S, int Nq,
                           const float* __restrict__ hres, const float* __restrict__ g,
                           const float* __restrict__ b, float* __restrict__ out) {
    __shared__ float red[D];
    __shared__ float red2[D];
    int q = blockIdx.x;
    int d = threadIdx.x;
    int h = d >> 4;
    int i = d & 15;
    int rowbase = q * 4 + h;

    float M = -CUDART_INF_F;
    for (int s = 0; s < S; s++) M = fmaxf(M, part[(size_t)(s * Nq * 4 + rowbase) * 18]);
    float num = 0.f, den = 0.f;
    for (int s = 0; s < S; s++) {
        const float* pp = part + (size_t)(s * Nq * 4 + rowbase) * 18;
        float e = __expf(pp[0] - M);
        den += e * pp[1];
        num += e * pp[2 + i];
    }
    float val = num / den + hres[(size_t)q * D + d];

    red[d] = val;
    red2[d] = val * val;
    __syncthreads();
    for (int off = 32; off >= 1; off >>= 1) {
        if (d < off) {
            red[d] += red[d + off];
            red2[d] += red2[d + off];
        }
        __syncthreads();
    }
    float mu = red[0] * (1.f / 64.f);
    float var = red2[0] * (1.f / 64.f) - mu * mu;
    float r = rsqrtf(var + 1e-5f);
    out[(size_t)q * D + d] = (val - mu) * r * g[d] + b[d];
}

// ---------------- launch ----------------
extern "C" void kernel_launch(void* const* d_in, const int* in_sizes, int n_in,
                              void* d_out, int out_size) {
    const float* x_mol = (const float*)d_in[0];
    const int* ei_mol = (const int*)d_in[1];
    const float* ea_mol = (const float*)d_in[2];
    const float* x_prot = (const float*)d_in[3];
    const int* ei_prot = (const int*)d_in[4];
    const float* ea_prot = (const float*)d_in[5];
    const float* mol_w1 = (const float*)d_in[6];
    const float* mol_b1 = (const float*)d_in[7];
    const float* mol_w2 = (const float*)d_in[8];
    const float* mol_b2 = (const float*)d_in[9];
    const float* prot_w1 = (const float*)d_in[10];
    const float* prot_b1 = (const float*)d_in[11];
    const float* prot_w2 = (const float*)d_in[12];
    const float* prot_b2 = (const float*)d_in[13];
    const float* mp_wq = (const float*)d_in[14];
    const float* mp_bq = (const float*)d_in[15];
    const float* mp_wk = (const float*)d_in[16];
    const float* mp_bk = (const float*)d_in[17];
    const float* mp_wv = (const float*)d_in[18];
    const float* mp_bv = (const float*)d_in[19];
    const float* pm_wq = (const float*)d_in[20];
    const float* pm_bq = (const float*)d_in[21];
    const float* pm_wk = (const float*)d_in[22];
    const float* pm_bk = (const float*)d_in[23];
    const float* pm_wv = (const float*)d_in[24];
    const float* pm_bv = (const float*)d_in[25];
    const float* ln_mol_g = (const float*)d_in[26];
    const float* ln_mol_b = (const float*)d_in[27];
    const float* ln_prot_g = (const float*)d_in[28];
    const float* ln_prot_b = (const float*)d_in[29];

    int E_mol = in_sizes[1] / 2;
    int E_prot = in_sizes[4] / 2;
    float* out = (float*)d_out;

    float *aggr_mol, *cnt_mol, *aggr_prot, *cnt_prot;
    float *hmol, *hprot, *Qm, *Km, *Vm, *Qp, *Kp, *Vp, *part_mol, *part_prot;
    cudaGetSymbolAddress((void**)&aggr_mol, g_aggr_mol);
    cudaGetSymbolAddress((void**)&cnt_mol, g_cnt_mol);
    cudaGetSymbolAddress((void**)&aggr_prot, g_aggr_prot);
    cudaGetSymbolAddress((void**)&cnt_prot, g_cnt_prot);
    cudaGetSymbolAddress((void**)&hmol, g_hmol);
    cudaGetSymbolAddress((void**)&hprot, g_hprot);
    cudaGetSymbolAddress((void**)&Qm, g_Qm);
    cudaGetSymbolAddress((void**)&Km, g_Km);
    cudaGetSymbolAddress((void**)&Vm, g_Vm);
    cudaGetSymbolAddress((void**)&Qp, g_Qp);
    cudaGetSymbolAddress((void**)&Kp, g_Kp);
    cudaGetSymbolAddress((void**)&Vp, g_Vp);
    cudaGetSymbolAddress((void**)&part_mol, g_part_mol);
    cudaGetSymbolAddress((void**)&part_prot, g_part_prot);

    static int smem_set = 0;
    if (!smem_set) {
        cudaFuncSetAttribute(attn_all, cudaFuncAttributeMaxDynamicSharedMemorySize, 65536);
        smem_set = 1;
    }

    zero_all<<<256, 256>>>();

    int total_scatter = (E_mol + E_prot) * 16;
    edge_scatter_all<<<(total_scatter + 255) / 256, 256>>>(
        x_mol, ei_mol, ea_mol, aggr_mol, cnt_mol, E_mol,
        x_prot, ei_prot, ea_prot, aggr_prot, cnt_prot, E_prot);

    gine_all<<<NM / 8 + NP / 8, 256>>>(
        x_mol, aggr_mol, cnt_mol, mol_w1, mol_b1, mol_w2, mol_b2,
        mp_wq, mp_bq, pm_wk, pm_bk, pm_wv, pm_bv, hmol, Qm, Km, Vm,
        x_prot, aggr_prot, cnt_prot, prot_w1, prot_b1, prot_w2, prot_b2,
        pm_wq, pm_bq, mp_wk, mp_bk, mp_wv, mp_bv, hprot, Qp, Kp, Vp);

    attn_all<<<1024, 128, 65536>>>(Qm, Kp, Vp, part_mol, Qp, Km, Vm, part_prot);

    combine_ln<<<NM, 64>>>(part_mol, SPLIT_M, NM, hmol, ln_mol_g, ln_mol_b, out);
    combine_ln<<<NP, 64>>>(part_prot, SPLIT_P, NP, hprot, ln_prot_g, ln_prot_b, out + NM * D);
}